// round 1
// baseline (speedup 1.0000x reference)
#include <cuda_runtime.h>
#include <cuda_bf16.h>

#define N_MESH_C 10000
#define N_GRID_C 100000
#define N_EDGE_C 300000
#define DIM_C    256

// Scratch (device globals: allocation-free per harness rules)
__device__ float g_H1[(size_t)N_EDGE_C * DIM_C];   // edge hidden, 307 MB
__device__ float g_agg[(size_t)N_GRID_C * DIM_C];  // scatter-sum accumulator, 102 MB
__device__ float g_H2[(size_t)N_GRID_C * DIM_C];   // grid hidden, 102 MB

// ---------------------------------------------------------------------------
// Zero the aggregation buffer. 25,600,000 floats = 6,400,000 float4.
// ---------------------------------------------------------------------------
__global__ void zero_agg_kernel() {
    size_t i = ((size_t)blockIdx.x * blockDim.x + threadIdx.x) * 4;
    float4 z = make_float4(0.f, 0.f, 0.f, 0.f);
    *(float4*)&g_agg[i] = z;
}

// ---------------------------------------------------------------------------
// Register-blocked SGEMM: C[M, 256] = op(A[M, K] @ W[K, 256] + bias)
// BM=128, BN=128, BK=16, 256 threads, 8x8 microtile per thread.
//
// MODE 0 (EDGE_L1): A row r = concat(mesh_x[src[r]], grid_x[dst[r]]), K=512.
//                   ReLU; write g_H1.
// MODE 1 (EDGE_L2): A = g_H1, K=256. +bias, atomicAdd into g_agg[dst[r]].
// MODE 2 (GRID_L1): A row r = concat(grid_x[r], g_agg[r]), K=512.
//                   ReLU; write g_H2.
// MODE 3 (GRID_L2): A = g_H2, K=256. +bias +grid_x residual; write out.
// ---------------------------------------------------------------------------
constexpr int BM = 128, BN = 128, BK = 16, TM = 8, TN = 8;

template<int MODE, int K>
__launch_bounds__(256, 2)
__global__ void gemm_kernel(
    const float* __restrict__ A0,     // mesh_x (M0) | grid_x (M2)
    const int*   __restrict__ isrc,   // edge_src (M0)
    const int*   __restrict__ idst,   // edge_dst (M0 gather, M1 scatter)
    const float* __restrict__ W,      // [K, 256]
    const float* __restrict__ bias,   // [256]
    float*       __restrict__ out,    // d_out (M3)
    const float* __restrict__ resid,  // grid_x (M3)
    int M)
{
    __shared__ float As[BK][BM];
    __shared__ float Bs[BK][BN];
    __shared__ int s_i0[BM];
    __shared__ int s_i1[BM];

    const int tid = threadIdx.x;
    const int m0 = blockIdx.x * BM;
    const int n0 = blockIdx.y * BN;

    if (MODE == 0) {
        if (tid < BM) {
            int rg = m0 + tid;
            int cl = rg < M ? rg : (M - 1);
            s_i0[tid] = isrc[cl];
            s_i1[tid] = idst[cl];
        }
    }
    __syncthreads();

    const int tm = (tid >> 4) * TM;   // 0..120
    const int tn = (tid & 15) * TN;   // 0..120

    float acc[TM][TN];
    #pragma unroll
    for (int i = 0; i < TM; ++i)
        #pragma unroll
        for (int j = 0; j < TN; ++j)
            acc[i][j] = 0.f;

    for (int kt = 0; kt < K; kt += BK) {
        // ---- load B tile: 16 x 128 (coalesced float4) ----
        #pragma unroll
        for (int it = 0; it < 2; ++it) {
            int li = tid + it * 256;
            int r = li >> 5;            // k within tile, 0..15
            int c = (li & 31) << 2;     // n within tile, step 4
            float4 v = *(const float4*)&W[(size_t)(kt + r) * DIM_C + n0 + c];
            *(float4*)&Bs[r][c] = v;
        }
        // ---- load A tile: 128 rows x 16 k (gathered), store transposed ----
        #pragma unroll
        for (int it = 0; it < 2; ++it) {
            int li = tid + it * 256;
            int r  = li >> 2;           // row within tile, 0..127
            int c4 = (li & 3) << 2;     // k offset within tile: 0,4,8,12
            int kk = kt + c4;
            int rg = m0 + r;
            const float* rowp;
            if (MODE == 0) {
                if (kk < DIM_C) rowp = A0    + (size_t)s_i0[r] * DIM_C + kk;
                else            rowp = resid + (size_t)s_i1[r] * DIM_C + (kk - DIM_C);
            } else if (MODE == 2) {
                int rr = rg < M ? rg : 0;
                if (kk < DIM_C) rowp = A0    + (size_t)rr * DIM_C + kk;
                else            rowp = g_agg + (size_t)rr * DIM_C + (kk - DIM_C);
            } else if (MODE == 1) {
                int rr = rg < M ? rg : 0;
                rowp = g_H1 + (size_t)rr * DIM_C + kk;
            } else {
                int rr = rg < M ? rg : 0;
                rowp = g_H2 + (size_t)rr * DIM_C + kk;
            }
            float4 v = *(const float4*)rowp;
            As[c4 + 0][r] = v.x;
            As[c4 + 1][r] = v.y;
            As[c4 + 2][r] = v.z;
            As[c4 + 3][r] = v.w;
        }
        __syncthreads();

        // ---- 8x8 microtile FMA ----
        #pragma unroll
        for (int k = 0; k < BK; ++k) {
            float a[TM], b[TN];
            *(float4*)&a[0] = *(const float4*)&As[k][tm];
            *(float4*)&a[4] = *(const float4*)&As[k][tm + 4];
            *(float4*)&b[0] = *(const float4*)&Bs[k][tn];
            *(float4*)&b[4] = *(const float4*)&Bs[k][tn + 4];
            #pragma unroll
            for (int i = 0; i < TM; ++i)
                #pragma unroll
                for (int j = 0; j < TN; ++j)
                    acc[i][j] = fmaf(a[i], b[j], acc[i][j]);
        }
        __syncthreads();
    }

    // ---- epilogue ----
    float bv[TN];
    *(float4*)&bv[0] = *(const float4*)&bias[n0 + tn];
    *(float4*)&bv[4] = *(const float4*)&bias[n0 + tn + 4];

    if (MODE == 1) {
        // scatter-add edge messages into grid accumulator
        #pragma unroll
        for (int i = 0; i < TM; ++i) {
            int rg = m0 + tm + i;
            if (rg < M) {
                int d = idst[rg];
                float* dst = &g_agg[(size_t)d * DIM_C + n0 + tn];
                #pragma unroll
                for (int j = 0; j < TN; ++j)
                    atomicAdd(dst + j, acc[i][j] + bv[j]);
            }
        }
    } else {
        #pragma unroll
        for (int i = 0; i < TM; ++i) {
            int rg = m0 + tm + i;
            if (rg >= M) continue;
            float v[TN];
            #pragma unroll
            for (int j = 0; j < TN; ++j) {
                float x = acc[i][j] + bv[j];
                if (MODE == 0 || MODE == 2) x = fmaxf(x, 0.f);
                v[j] = x;
            }
            float* op;
            if (MODE == 0)      op = &g_H1[(size_t)rg * DIM_C + n0 + tn];
            else if (MODE == 2) op = &g_H2[(size_t)rg * DIM_C + n0 + tn];
            else {
                op = &out[(size_t)rg * DIM_C + n0 + tn];
                const float* rp = &resid[(size_t)rg * DIM_C + n0 + tn];
                #pragma unroll
                for (int j = 0; j < TN; ++j) v[j] += rp[j];
            }
            *(float4*)op       = *(float4*)&v[0];
            *(float4*)(op + 4) = *(float4*)&v[4];
        }
    }
}

extern "C" void kernel_launch(void* const* d_in, const int* in_sizes, int n_in,
                              void* d_out, int out_size) {
    const float* mesh_x   = (const float*)d_in[0];
    const float* grid_x   = (const float*)d_in[1];
    const int*   edge_src = (const int*)  d_in[2];
    const int*   edge_dst = (const int*)  d_in[3];
    const float* w1_e     = (const float*)d_in[4];
    const float* b1_e     = (const float*)d_in[5];
    const float* w2_e     = (const float*)d_in[6];
    const float* b2_e     = (const float*)d_in[7];
    const float* w1_g     = (const float*)d_in[8];
    const float* b1_g     = (const float*)d_in[9];
    const float* w2_g     = (const float*)d_in[10];
    const float* b2_g     = (const float*)d_in[11];
    float* out = (float*)d_out;

    // zero agg: 25.6e6 floats / (256 threads * 4) = 25000 blocks exactly
    zero_agg_kernel<<<25000, 256>>>();

    dim3 ge((N_EDGE_C + BM - 1) / BM, 2);
    dim3 gg((N_GRID_C + BM - 1) / BM, 2);

    // edge layer 1: relu(concat(mesh[src], grid[dst]) @ w1_e + b1_e) -> H1
    gemm_kernel<0, 512><<<ge, 256>>>(mesh_x, edge_src, edge_dst,
                                     w1_e, b1_e, nullptr, grid_x, N_EDGE_C);
    // edge layer 2 + scatter: (H1 @ w2_e + b2_e) atomically summed into agg[dst]
    gemm_kernel<1, 256><<<ge, 256>>>(nullptr, nullptr, edge_dst,
                                     w2_e, b2_e, nullptr, nullptr, N_EDGE_C);
    // grid layer 1: relu(concat(grid_x, agg) @ w1_g + b1_g) -> H2
    gemm_kernel<2, 512><<<gg, 256>>>(grid_x, nullptr, nullptr,
                                     w1_g, b1_g, nullptr, nullptr, N_GRID_C);
    // grid layer 2 + residual: grid_x + H2 @ w2_g + b2_g -> out
    gemm_kernel<3, 256><<<gg, 256>>>(nullptr, nullptr, nullptr,
                                     w2_g, b2_g, out, grid_x, N_GRID_C);
}

// round 3
// speedup vs baseline: 1.4735x; 1.4735x over previous
#include <cuda_runtime.h>
#include <cuda_bf16.h>
#include <cstdint>

#define N_MESH 10000
#define N_GRID 100000
#define N_EDGE 300000
#define DH     256

// ---------------- device scratch ---------------------------------------------
__device__ float g_H1[(size_t)N_EDGE * DH];
__device__ float g_H2[(size_t)N_GRID * DH];
__device__ float g_agg[(size_t)N_GRID * DH];
// transposed+split weights: layout Wt[n][k], bf16 hi and lo parts
__device__ __nv_bfloat16 g_Wh[(512 + 256 + 512 + 256) * DH];
__device__ __nv_bfloat16 g_Wl[(512 + 256 + 512 + 256) * DH];

// ---------------- helpers -----------------------------------------------------
__device__ __forceinline__ uint32_t smem_u32(const void* p) {
    uint32_t a;
    asm("{ .reg .u64 t; cvta.to.shared.u64 t, %1; cvt.u32.u64 %0, t; }"
        : "=r"(a) : "l"(p));
    return a;
}

#define LDSM_X4(r, addr)                                                     \
    asm volatile("ldmatrix.sync.aligned.m8n8.x4.shared.b16 {%0,%1,%2,%3}, [%4];" \
        : "=r"((r)[0]), "=r"((r)[1]), "=r"((r)[2]), "=r"((r)[3]) : "r"(addr))

#define MMA16816(c, a, b0, b1)                                               \
    asm volatile("mma.sync.aligned.m16n8k16.row.col.f32.bf16.bf16.f32 "      \
        "{%0,%1,%2,%3}, {%4,%5,%6,%7}, {%8,%9}, {%0,%1,%2,%3};"              \
        : "+f"((c)[0]), "+f"((c)[1]), "+f"((c)[2]), "+f"((c)[3])             \
        : "r"((a)[0]), "r"((a)[1]), "r"((a)[2]), "r"((a)[3]), "r"(b0), "r"(b1))

__device__ __forceinline__ uint32_t pack2_hi(float a, float b, float& ra, float& rb) {
    __nv_bfloat162 t = __floats2bfloat162_rn(a, b);
    ra = a - __bfloat162float(t.x);
    rb = b - __bfloat162float(t.y);
    return *(uint32_t*)&t;
}
__device__ __forceinline__ uint32_t pack2(float a, float b) {
    __nv_bfloat162 t = __floats2bfloat162_rn(a, b);
    return *(uint32_t*)&t;
}
__device__ __forceinline__ void red_add_v2(float* p, float x, float y) {
    asm volatile("red.global.add.v2.f32 [%0], {%1,%2};"
                 :: "l"(p), "f"(x), "f"(y) : "memory");
}

// ---------------- aux kernels -------------------------------------------------
__global__ void zero_agg_kernel() {
    size_t i = ((size_t)blockIdx.x * blockDim.x + threadIdx.x) * 4;
    *(float4*)&g_agg[i] = make_float4(0.f, 0.f, 0.f, 0.f);
}

// in[k][256] fp32 -> outh/outl[n][K] bf16 (transpose + hi/lo split)
__global__ void prep_w_kernel(const float* __restrict__ in,
                              __nv_bfloat16* __restrict__ outh,
                              __nv_bfloat16* __restrict__ outl, int K) {
    __shared__ float t[32][33];
    int bx = blockIdx.x * 32;   // n tile
    int by = blockIdx.y * 32;   // k tile
    int tx = threadIdx.x, ty = threadIdx.y;
    #pragma unroll
    for (int i = 0; i < 32; i += 8)
        t[ty + i][tx] = in[(size_t)(by + ty + i) * DH + bx + tx];
    __syncthreads();
    #pragma unroll
    for (int i = 0; i < 32; i += 8) {
        float v = t[tx][ty + i];
        __nv_bfloat16 h = __float2bfloat16(v);
        __nv_bfloat16 l = __float2bfloat16(v - __bfloat162float(h));
        size_t o = (size_t)(bx + ty + i) * K + by + tx;
        outh[o] = h;
        outl[o] = l;
    }
}

// ---------------- main GEMM ---------------------------------------------------
// C[M,256] = op(A[M,K] @ W[K,256] + bias), 3-term bf16 split via mma.sync.
// Block tile 128x128 (grid.y = 2), BK=32, 256 threads (8 warps, 4x2).
// MODE 0: A = concat(mesh_x[src], grid_x[dst]); relu -> g_H1
// MODE 1: A = g_H1; +bias, red.v2 scatter -> g_agg[dst]
// MODE 2: A = concat(grid_x, g_agg); relu -> g_H2
// MODE 3: A = g_H2; +bias +resid -> out
static constexpr int BK = 32;
static constexpr uint32_t RSTRIDE = 80;            // 64B row + 16B pad
static constexpr uint32_t MATB = 128 * RSTRIDE;    // 10240 bytes per matrix
static constexpr uint32_t BUFB = 4 * MATB;         // Ah,Al,Bh,Bl
static constexpr uint32_t TILES = 2048;
static constexpr uint32_t SMEM_SZ = TILES + 2 * BUFB;  // 83968

template<int MODE, int K>
__global__ __launch_bounds__(256, 1)
void mma_gemm(const float* __restrict__ A0,
              const int*   __restrict__ isrc,
              const int*   __restrict__ idst,
              const __nv_bfloat16* __restrict__ Wh,   // [256][K]
              const __nv_bfloat16* __restrict__ Wl,
              const float* __restrict__ bias,
              float*       __restrict__ out,
              const float* __restrict__ resid,
              int M)
{
    extern __shared__ char smem[];
    constexpr int NCH = K / BK;
    const uint32_t sb = smem_u32(smem);

    const int tid  = threadIdx.x;
    const int wid  = tid >> 5;
    const int lane = tid & 31;
    const int m0 = blockIdx.x * 128;
    const int n0 = blockIdx.y * 128;

    float* s_bias = (float*)(smem);          // 256 floats
    int*   s_src  = (int*)(smem + 1024);     // 128
    int*   s_dst  = (int*)(smem + 1536);     // 128

    s_bias[tid] = bias[tid];                 // 256 threads cover 256
    if (MODE == 0 && tid < 128) {
        int rg = m0 + tid;
        int cl = rg < M ? rg : (M - 1);
        s_src[tid] = isrc[cl];
        s_dst[tid] = idst[cl];
    }
    __syncthreads();

    // ---- chunk loader ----
    auto load_chunk = [&](int buf, int kt) {
        char* ab = smem + TILES + (uint32_t)buf * BUFB;
        // A: 128 rows x 32 floats -> split into Ah/Al bf16
        #pragma unroll
        for (int it = 0; it < 4; ++it) {
            int e = it * 256 + tid;
            int row = e >> 3;
            int c4 = (e & 7) * 4;
            const float* p;
            if (MODE == 0) {
                if (kt < DH) p = A0    + (size_t)s_src[row] * DH + kt + c4;
                else         p = resid + (size_t)s_dst[row] * DH + (kt - DH) + c4;
            } else if (MODE == 2) {
                int rr = m0 + row; if (rr >= M) rr = M - 1;
                if (kt < DH) p = A0    + (size_t)rr * DH + kt + c4;
                else         p = g_agg + (size_t)rr * DH + (kt - DH) + c4;
            } else if (MODE == 1) {
                int rr = m0 + row; if (rr >= M) rr = M - 1;
                p = g_H1 + (size_t)rr * DH + kt + c4;
            } else {
                int rr = m0 + row; if (rr >= M) rr = M - 1;
                p = g_H2 + (size_t)rr * DH + kt + c4;
            }
            float4 v = *(const float4*)p;
            float rx, ry, rz, rw;
            uint32_t h01 = pack2_hi(v.x, v.y, rx, ry);
            uint32_t h23 = pack2_hi(v.z, v.w, rz, rw);
            uint32_t l01 = pack2(rx, ry);
            uint32_t l23 = pack2(rz, rw);
            uint32_t off = (uint32_t)row * RSTRIDE + (uint32_t)c4 * 2;
            *(uint2*)(ab + off)        = make_uint2(h01, h23);
            *(uint2*)(ab + MATB + off) = make_uint2(l01, l23);
        }
        // B: 128 n-rows x 32 k bf16, straight copy of preconverted weights
        #pragma unroll
        for (int it = 0; it < 2; ++it) {
            int e = it * 256 + tid;
            int row = e >> 2;
            int q = e & 3;
            size_t g = (size_t)(n0 + row) * K + kt;
            uint32_t off = (uint32_t)row * RSTRIDE + (uint32_t)q * 16;
            *(uint4*)(ab + 2 * MATB + off) = *((const uint4*)(Wh + g) + q);
            *(uint4*)(ab + 3 * MATB + off) = *((const uint4*)(Wl + g) + q);
        }
    };

    const int wm = wid & 3;    // m sub-tile: 32 rows
    const int wn = wid >> 2;   // n sub-tile: 64 cols

    float acc[2][8][4];
    #pragma unroll
    for (int i = 0; i < 2; ++i)
        #pragma unroll
        for (int j = 0; j < 8; ++j)
            #pragma unroll
            for (int q = 0; q < 4; ++q)
                acc[i][j][q] = 0.f;

    load_chunk(0, 0);
    __syncthreads();

    for (int c = 0; c < NCH; ++c) {
        int buf = c & 1;
        if (c + 1 < NCH) load_chunk(buf ^ 1, (c + 1) * BK);

        const uint32_t tb = sb + TILES + (uint32_t)buf * BUFB;
        const uint32_t a_base = tb + (uint32_t)(wm * 32 + (lane & 15)) * RSTRIDE
                                   + (uint32_t)((lane >> 4) * 16);
        const uint32_t b_base = tb + 2 * MATB
                                   + (uint32_t)(wn * 64 + ((lane >> 4) & 1) * 8 + (lane & 7)) * RSTRIDE
                                   + (uint32_t)(((lane >> 3) & 1) * 16);
        #pragma unroll
        for (int s = 0; s < 2; ++s) {
            uint32_t ah[2][4], al[2][4];
            LDSM_X4(ah[0], a_base + s * 32);
            LDSM_X4(ah[1], a_base + 16 * RSTRIDE + s * 32);
            LDSM_X4(al[0], a_base + MATB + s * 32);
            LDSM_X4(al[1], a_base + MATB + 16 * RSTRIDE + s * 32);
            #pragma unroll
            for (int p = 0; p < 4; ++p) {
                uint32_t bh[4], bl[4];
                LDSM_X4(bh, b_base + (uint32_t)(p * 16) * RSTRIDE + s * 32);
                LDSM_X4(bl, b_base + MATB + (uint32_t)(p * 16) * RSTRIDE + s * 32);
                #pragma unroll
                for (int mt = 0; mt < 2; ++mt) {
                    MMA16816(acc[mt][2*p],   ah[mt], bh[0], bh[1]);
                    MMA16816(acc[mt][2*p+1], ah[mt], bh[2], bh[3]);
                    MMA16816(acc[mt][2*p],   al[mt], bh[0], bh[1]);
                    MMA16816(acc[mt][2*p+1], al[mt], bh[2], bh[3]);
                    MMA16816(acc[mt][2*p],   ah[mt], bl[0], bl[1]);
                    MMA16816(acc[mt][2*p+1], ah[mt], bl[2], bl[3]);
                }
            }
        }
        __syncthreads();
    }

    // ---- epilogue ----
    #pragma unroll
    for (int mt = 0; mt < 2; ++mt) {
        #pragma unroll
        for (int nt = 0; nt < 8; ++nt) {
            int r0  = m0 + wm * 32 + mt * 16 + (lane >> 2);
            int r1  = r0 + 8;
            int col = n0 + (wn * 64 + (nt >> 1) * 16 + (nt & 1) * 8) + (lane & 3) * 2;
            float b0 = s_bias[col - n0 + (n0 ? 128 : 0)];
            // s_bias holds all 256 biases indexed globally:
            b0 = s_bias[col & 255];
            float b1 = s_bias[(col + 1) & 255];
            float v00 = acc[mt][nt][0] + b0, v01 = acc[mt][nt][1] + b1;
            float v10 = acc[mt][nt][2] + b0, v11 = acc[mt][nt][3] + b1;
            if (MODE == 0 || MODE == 2) {
                float* H = (MODE == 0) ? g_H1 : g_H2;
                if (r0 < M) {
                    float2 w = make_float2(fmaxf(v00, 0.f), fmaxf(v01, 0.f));
                    *(float2*)&H[(size_t)r0 * DH + col] = w;
                }
                if (r1 < M) {
                    float2 w = make_float2(fmaxf(v10, 0.f), fmaxf(v11, 0.f));
                    *(float2*)&H[(size_t)r1 * DH + col] = w;
                }
            } else if (MODE == 1) {
                if (r0 < M) red_add_v2(&g_agg[(size_t)idst[r0] * DH + col], v00, v01);
                if (r1 < M) red_add_v2(&g_agg[(size_t)idst[r1] * DH + col], v10, v11);
            } else {
                if (r0 < M) {
                    float2 rv = *(const float2*)&resid[(size_t)r0 * DH + col];
                    *(float2*)&out[(size_t)r0 * DH + col] = make_float2(v00 + rv.x, v01 + rv.y);
                }
                if (r1 < M) {
                    float2 rv = *(const float2*)&resid[(size_t)r1 * DH + col];
                    *(float2*)&out[(size_t)r1 * DH + col] = make_float2(v10 + rv.x, v11 + rv.y);
                }
            }
        }
    }
}

// ---------------- launch -------------------------------------------------------
extern "C" void kernel_launch(void* const* d_in, const int* in_sizes, int n_in,
                              void* d_out, int out_size) {
    const float* mesh_x   = (const float*)d_in[0];
    const float* grid_x   = (const float*)d_in[1];
    const int*   edge_src = (const int*)  d_in[2];
    const int*   edge_dst = (const int*)  d_in[3];
    const float* w1_e = (const float*)d_in[4];
    const float* b1_e = (const float*)d_in[5];
    const float* w2_e = (const float*)d_in[6];
    const float* b2_e = (const float*)d_in[7];
    const float* w1_g = (const float*)d_in[8];
    const float* b1_g = (const float*)d_in[9];
    const float* w2_g = (const float*)d_in[10];
    const float* b2_g = (const float*)d_in[11];
    float* out = (float*)d_out;

    __nv_bfloat16 *wh, *wl;
    cudaGetSymbolAddress((void**)&wh, g_Wh);
    cudaGetSymbolAddress((void**)&wl, g_Wl);
    __nv_bfloat16* wh_e1 = wh;                    __nv_bfloat16* wl_e1 = wl;
    __nv_bfloat16* wh_e2 = wh + 256 * 512;        __nv_bfloat16* wl_e2 = wl + 256 * 512;
    __nv_bfloat16* wh_g1 = wh_e2 + 256 * 256;     __nv_bfloat16* wl_g1 = wl_e2 + 256 * 256;
    __nv_bfloat16* wh_g2 = wh_g1 + 256 * 512;     __nv_bfloat16* wl_g2 = wl_g1 + 256 * 512;

    static bool attr_set = false;
    if (!attr_set) {
        cudaFuncSetAttribute(mma_gemm<0,512>, cudaFuncAttributeMaxDynamicSharedMemorySize, SMEM_SZ);
        cudaFuncSetAttribute(mma_gemm<1,256>, cudaFuncAttributeMaxDynamicSharedMemorySize, SMEM_SZ);
        cudaFuncSetAttribute(mma_gemm<2,512>, cudaFuncAttributeMaxDynamicSharedMemorySize, SMEM_SZ);
        cudaFuncSetAttribute(mma_gemm<3,256>, cudaFuncAttributeMaxDynamicSharedMemorySize, SMEM_SZ);
        attr_set = true;
    }

    zero_agg_kernel<<<25000, 256>>>();
    prep_w_kernel<<<dim3(8, 16), dim3(32, 8)>>>(w1_e, wh_e1, wl_e1, 512);
    prep_w_kernel<<<dim3(8,  8), dim3(32, 8)>>>(w2_e, wh_e2, wl_e2, 256);
    prep_w_kernel<<<dim3(8, 16), dim3(32, 8)>>>(w1_g, wh_g1, wl_g1, 512);
    prep_w_kernel<<<dim3(8,  8), dim3(32, 8)>>>(w2_g, wh_g2, wl_g2, 256);

    const int GE = (N_EDGE + 127) / 128;   // 2344
    const int GG = (N_GRID + 127) / 128;   // 782

    mma_gemm<0,512><<<dim3(GE,2), 256, SMEM_SZ>>>(mesh_x, edge_src, edge_dst,
                                                  wh_e1, wl_e1, b1_e, nullptr, grid_x, N_EDGE);
    mma_gemm<1,256><<<dim3(GE,2), 256, SMEM_SZ>>>(nullptr, nullptr, edge_dst,
                                                  wh_e2, wl_e2, b2_e, nullptr, nullptr, N_EDGE);
    mma_gemm<2,512><<<dim3(GG,2), 256, SMEM_SZ>>>(grid_x, nullptr, nullptr,
                                                  wh_g1, wl_g1, b1_g, nullptr, nullptr, N_GRID);
    mma_gemm<3,256><<<dim3(GG,2), 256, SMEM_SZ>>>(nullptr, nullptr, nullptr,
                                                  wh_g2, wl_g2, b2_g, out, grid_x, N_GRID);
}

// round 4
// speedup vs baseline: 2.2302x; 1.5136x over previous
#include <cuda_runtime.h>
#include <cuda_fp16.h>
#include <cstdint>

#define N_MESH 10000
#define N_GRID 100000
#define N_EDGE 300000
#define DH     256

// ---------------- device scratch ----------------------------------------------
__device__ float g_agg[(size_t)N_GRID * DH];                       // fp32 scatter acc
__device__ __align__(16) __half g_mxh[(size_t)N_MESH * DH];
__device__ __align__(16) __half g_mxl[(size_t)N_MESH * DH];
__device__ __align__(16) __half g_gxh[(size_t)N_GRID * DH];
__device__ __align__(16) __half g_gxl[(size_t)N_GRID * DH];
__device__ __align__(16) __half g_aggh[(size_t)N_GRID * DH];
__device__ __align__(16) __half g_aggl[(size_t)N_GRID * DH];
__device__ __align__(16) __half g_H1h[(size_t)N_EDGE * DH];
__device__ __align__(16) __half g_H1l[(size_t)N_EDGE * DH];
__device__ __align__(16) __half g_H2h[(size_t)N_GRID * DH];
__device__ __align__(16) __half g_H2l[(size_t)N_GRID * DH];
__device__ __align__(16) __half g_Wh[(512 + 256 + 512 + 256) * DH];
__device__ __align__(16) __half g_Wl[(512 + 256 + 512 + 256) * DH];

// ---------------- helpers -------------------------------------------------------
__device__ __forceinline__ uint32_t smem_u32(const void* p) {
    uint32_t a;
    asm("{ .reg .u64 t; cvta.to.shared.u64 t, %1; cvt.u32.u64 %0, t; }"
        : "=r"(a) : "l"(p));
    return a;
}

#define LDSM_X4(r, addr)                                                     \
    asm volatile("ldmatrix.sync.aligned.m8n8.x4.shared.b16 {%0,%1,%2,%3}, [%4];" \
        : "=r"((r)[0]), "=r"((r)[1]), "=r"((r)[2]), "=r"((r)[3]) : "r"(addr))

#define MMA16816(c, a, b0, b1)                                               \
    asm volatile("mma.sync.aligned.m16n8k16.row.col.f32.f16.f16.f32 "        \
        "{%0,%1,%2,%3}, {%4,%5,%6,%7}, {%8,%9}, {%0,%1,%2,%3};"              \
        : "+f"((c)[0]), "+f"((c)[1]), "+f"((c)[2]), "+f"((c)[3])             \
        : "r"((a)[0]), "r"((a)[1]), "r"((a)[2]), "r"((a)[3]), "r"(b0), "r"(b1))

#define CP16(dst, src) \
    asm volatile("cp.async.cg.shared.global [%0], [%1], 16;" :: "r"(dst), "l"(src))
#define CP_COMMIT() asm volatile("cp.async.commit_group;")
#define CP_WAIT1()  asm volatile("cp.async.wait_group 1;")
#define CP_WAIT0()  asm volatile("cp.async.wait_group 0;")

__device__ __forceinline__ void red_add_v2(float* p, float x, float y) {
    asm volatile("red.global.add.v2.f32 [%0], {%1,%2};"
                 :: "l"(p), "f"(x), "f"(y) : "memory");
}

// ---------------- aux kernels ----------------------------------------------------
__global__ void zero_agg_kernel() {
    size_t i = ((size_t)blockIdx.x * blockDim.x + threadIdx.x) * 4;
    *(float4*)&g_agg[i] = make_float4(0.f, 0.f, 0.f, 0.f);
}

// elementwise fp32 -> fp16 hi/lo split (vectorized by 4)
__global__ void split_kernel(const float4* __restrict__ in,
                             uint2* __restrict__ h, uint2* __restrict__ l, int n4) {
    int i = blockIdx.x * blockDim.x + threadIdx.x;
    if (i >= n4) return;
    float4 v = in[i];
    __half2 h01 = __floats2half2_rn(v.x, v.y);
    __half2 h23 = __floats2half2_rn(v.z, v.w);
    __half2 l01 = __floats2half2_rn(v.x - __low2float(h01), v.y - __high2float(h01));
    __half2 l23 = __floats2half2_rn(v.z - __low2float(h23), v.w - __high2float(h23));
    h[i] = make_uint2(*(uint32_t*)&h01, *(uint32_t*)&h23);
    l[i] = make_uint2(*(uint32_t*)&l01, *(uint32_t*)&l23);
}

// weights: in[k][256] fp32 -> outh/outl[n][K] fp16 (transpose + split)
__global__ void prep_w_kernel(const float* __restrict__ in,
                              __half* __restrict__ outh,
                              __half* __restrict__ outl, int K) {
    __shared__ float t[32][33];
    int bx = blockIdx.x * 32, by = blockIdx.y * 32;
    int tx = threadIdx.x, ty = threadIdx.y;
    #pragma unroll
    for (int i = 0; i < 32; i += 8)
        t[ty + i][tx] = in[(size_t)(by + ty + i) * DH + bx + tx];
    __syncthreads();
    #pragma unroll
    for (int i = 0; i < 32; i += 8) {
        float v = t[tx][ty + i];
        __half hh = __float2half_rn(v);
        __half ll = __float2half_rn(v - __half2float(hh));
        size_t o = (size_t)(bx + ty + i) * K + by + tx;
        outh[o] = hh;
        outl[o] = ll;
    }
}

// ---------------- main GEMM -------------------------------------------------------
// C[M,256] = op(A[M,K] @ W[K,256] + bias), fp16 3-term split via mma.sync,
// all operands preconverted fp16 hi/lo in gmem, pure cp.async loader.
// MODE 0: A = concat(mesh[src], grid[dst]); relu -> g_H1{h,l}
// MODE 1: A = g_H1; +bias, red.v2 scatter -> g_agg (fp32)
// MODE 2: A = concat(grid, agg); relu -> g_H2{h,l}
// MODE 3: A = g_H2; +bias +resid -> out (fp32)
static constexpr int BK = 32;
static constexpr uint32_t RSTRIDE = 80;           // 64B data + 16B pad (conflict-free)
static constexpr uint32_t MATB = 128 * RSTRIDE;   // 10240 B
static constexpr uint32_t BUFB = 4 * MATB;        // Ah, Al, Bh, Bl
static constexpr uint32_t TILES = 2048;
static constexpr uint32_t SMEM_SZ = TILES + 2 * BUFB;   // 83968

template<int MODE, int K>
__global__ __launch_bounds__(256, 1)
void mma_gemm(const int*   __restrict__ isrc,
              const int*   __restrict__ idst,
              const __half* __restrict__ Wh,    // [256][K]
              const __half* __restrict__ Wl,
              const float* __restrict__ bias,
              float*       __restrict__ out,
              const float* __restrict__ resid,
              int M)
{
    extern __shared__ char smem[];
    constexpr int NCH = K / BK;
    const uint32_t sb = smem_u32(smem);

    const int tid  = threadIdx.x;
    const int wid  = tid >> 5;
    const int lane = tid & 31;
    const int m0 = blockIdx.x * 128;
    const int n0 = blockIdx.y * 128;

    float* s_bias = (float*)(smem);
    int*   s_src  = (int*)(smem + 1024);
    int*   s_dst  = (int*)(smem + 1536);

    s_bias[tid] = bias[tid];
    if (MODE == 0 && tid < 128) {
        int rg = m0 + tid;
        int cl = rg < M ? rg : (M - 1);
        s_src[tid] = isrc[cl];
        s_dst[tid] = idst[cl];
    }
    __syncthreads();

    // ---- async chunk loader: 8x cp.async(16B) per thread ----
    auto load_chunk = [&](int buf, int kt) {
        const uint32_t ab = sb + TILES + (uint32_t)buf * BUFB;
        #pragma unroll
        for (int it = 0; it < 2; ++it) {
            int e = it * 256 + tid;      // 0..511
            int row = e >> 2;
            int cq = e & 3;
            const __half *ph, *pl;
            int kk;
            if (MODE == 0) {
                if (kt < DH) { size_t r = (size_t)s_src[row] * DH; ph = g_mxh + r; pl = g_mxl + r; kk = kt; }
                else         { size_t r = (size_t)s_dst[row] * DH; ph = g_gxh + r; pl = g_gxl + r; kk = kt - DH; }
            } else if (MODE == 2) {
                int rr = m0 + row; if (rr >= M) rr = M - 1;
                size_t r = (size_t)rr * DH;
                if (kt < DH) { ph = g_gxh + r;  pl = g_gxl + r;  kk = kt; }
                else         { ph = g_aggh + r; pl = g_aggl + r; kk = kt - DH; }
            } else if (MODE == 1) {
                int rr = m0 + row; if (rr >= M) rr = M - 1;
                size_t r = (size_t)rr * DH;
                ph = g_H1h + r; pl = g_H1l + r; kk = kt;
            } else {
                int rr = m0 + row; if (rr >= M) rr = M - 1;
                size_t r = (size_t)rr * DH;
                ph = g_H2h + r; pl = g_H2l + r; kk = kt;
            }
            uint32_t off = (uint32_t)row * RSTRIDE + (uint32_t)cq * 16;
            CP16(ab + off,        ph + kk + cq * 8);
            CP16(ab + MATB + off, pl + kk + cq * 8);
        }
        #pragma unroll
        for (int it = 0; it < 2; ++it) {
            int e = it * 256 + tid;
            int row = e >> 2;
            int cq = e & 3;
            size_t g = (size_t)(n0 + row) * K + kt + cq * 8;
            uint32_t off = (uint32_t)row * RSTRIDE + (uint32_t)cq * 16;
            CP16(ab + 2 * MATB + off, Wh + g);
            CP16(ab + 3 * MATB + off, Wl + g);
        }
        CP_COMMIT();
    };

    const int wm = wid & 3;
    const int wn = wid >> 2;

    float acc[2][8][4];
    #pragma unroll
    for (int i = 0; i < 2; ++i)
        #pragma unroll
        for (int j = 0; j < 8; ++j)
            #pragma unroll
            for (int q = 0; q < 4; ++q)
                acc[i][j][q] = 0.f;

    load_chunk(0, 0);

    for (int c = 0; c < NCH; ++c) {
        int buf = c & 1;
        if (c + 1 < NCH) { load_chunk(buf ^ 1, (c + 1) * BK); CP_WAIT1(); }
        else             { CP_WAIT0(); }
        __syncthreads();

        const uint32_t tb = sb + TILES + (uint32_t)buf * BUFB;
        const uint32_t a_base = tb + (uint32_t)(wm * 32 + (lane & 15)) * RSTRIDE
                                   + (uint32_t)((lane >> 4) * 16);
        const uint32_t b_base = tb + 2 * MATB
                                   + (uint32_t)(wn * 64 + ((lane >> 4) & 1) * 8 + (lane & 7)) * RSTRIDE
                                   + (uint32_t)(((lane >> 3) & 1) * 16);
        #pragma unroll
        for (int s = 0; s < 2; ++s) {
            uint32_t ah[2][4], al[2][4];
            LDSM_X4(ah[0], a_base + s * 32);
            LDSM_X4(ah[1], a_base + 16 * RSTRIDE + s * 32);
            LDSM_X4(al[0], a_base + MATB + s * 32);
            LDSM_X4(al[1], a_base + MATB + 16 * RSTRIDE + s * 32);
            #pragma unroll
            for (int p = 0; p < 4; ++p) {
                uint32_t bh[4], bl[4];
                LDSM_X4(bh, b_base + (uint32_t)(p * 16) * RSTRIDE + s * 32);
                LDSM_X4(bl, b_base + MATB + (uint32_t)(p * 16) * RSTRIDE + s * 32);
                // 12 MMAs cycling 4 accumulator groups (RAW distance 4)
                MMA16816(acc[0][2*p],   ah[0], bh[0], bh[1]);
                MMA16816(acc[1][2*p],   ah[1], bh[0], bh[1]);
                MMA16816(acc[0][2*p+1], ah[0], bh[2], bh[3]);
                MMA16816(acc[1][2*p+1], ah[1], bh[2], bh[3]);
                MMA16816(acc[0][2*p],   al[0], bh[0], bh[1]);
                MMA16816(acc[1][2*p],   al[1], bh[0], bh[1]);
                MMA16816(acc[0][2*p+1], al[0], bh[2], bh[3]);
                MMA16816(acc[1][2*p+1], al[1], bh[2], bh[3]);
                MMA16816(acc[0][2*p],   ah[0], bl[0], bl[1]);
                MMA16816(acc[1][2*p],   ah[1], bl[0], bl[1]);
                MMA16816(acc[0][2*p+1], ah[0], bl[2], bl[3]);
                MMA16816(acc[1][2*p+1], ah[1], bl[2], bl[3]);
            }
        }
        __syncthreads();
    }

    // ---- epilogue ----
    #pragma unroll
    for (int mt = 0; mt < 2; ++mt) {
        #pragma unroll
        for (int nt = 0; nt < 8; ++nt) {
            int r0  = m0 + wm * 32 + mt * 16 + (lane >> 2);
            int r1  = r0 + 8;
            int col = n0 + (wn * 64 + (nt >> 1) * 16 + (nt & 1) * 8) + (lane & 3) * 2;
            float b0 = s_bias[col & 255];
            float b1 = s_bias[(col + 1) & 255];
            float v00 = acc[mt][nt][0] + b0, v01 = acc[mt][nt][1] + b1;
            float v10 = acc[mt][nt][2] + b0, v11 = acc[mt][nt][3] + b1;
            if (MODE == 0 || MODE == 2) {
                __half* Hh = (MODE == 0) ? g_H1h : g_H2h;
                __half* Hl = (MODE == 0) ? g_H1l : g_H2l;
                if (r0 < M) {
                    float a = fmaxf(v00, 0.f), b = fmaxf(v01, 0.f);
                    __half2 hh = __floats2half2_rn(a, b);
                    __half2 ll = __floats2half2_rn(a - __low2float(hh), b - __high2float(hh));
                    *(__half2*)&Hh[(size_t)r0 * DH + col] = hh;
                    *(__half2*)&Hl[(size_t)r0 * DH + col] = ll;
                }
                if (r1 < M) {
                    float a = fmaxf(v10, 0.f), b = fmaxf(v11, 0.f);
                    __half2 hh = __floats2half2_rn(a, b);
                    __half2 ll = __floats2half2_rn(a - __low2float(hh), b - __high2float(hh));
                    *(__half2*)&Hh[(size_t)r1 * DH + col] = hh;
                    *(__half2*)&Hl[(size_t)r1 * DH + col] = ll;
                }
            } else if (MODE == 1) {
                if (r0 < M) red_add_v2(&g_agg[(size_t)idst[r0] * DH + col], v00, v01);
                if (r1 < M) red_add_v2(&g_agg[(size_t)idst[r1] * DH + col], v10, v11);
            } else {
                if (r0 < M) {
                    float2 rv = *(const float2*)&resid[(size_t)r0 * DH + col];
                    *(float2*)&out[(size_t)r0 * DH + col] = make_float2(v00 + rv.x, v01 + rv.y);
                }
                if (r1 < M) {
                    float2 rv = *(const float2*)&resid[(size_t)r1 * DH + col];
                    *(float2*)&out[(size_t)r1 * DH + col] = make_float2(v10 + rv.x, v11 + rv.y);
                }
            }
        }
    }
}

// ---------------- launch -----------------------------------------------------------
extern "C" void kernel_launch(void* const* d_in, const int* in_sizes, int n_in,
                              void* d_out, int out_size) {
    const float* mesh_x   = (const float*)d_in[0];
    const float* grid_x   = (const float*)d_in[1];
    const int*   edge_src = (const int*)  d_in[2];
    const int*   edge_dst = (const int*)  d_in[3];
    const float* w1_e = (const float*)d_in[4];
    const float* b1_e = (const float*)d_in[5];
    const float* w2_e = (const float*)d_in[6];
    const float* b2_e = (const float*)d_in[7];
    const float* w1_g = (const float*)d_in[8];
    const float* b1_g = (const float*)d_in[9];
    const float* w2_g = (const float*)d_in[10];
    const float* b2_g = (const float*)d_in[11];
    float* out = (float*)d_out;

    __half *wh, *wl, *mxh, *mxl, *gxh, *gxl, *aggh, *aggl;
    float* aggf;
    cudaGetSymbolAddress((void**)&wh,   g_Wh);
    cudaGetSymbolAddress((void**)&wl,   g_Wl);
    cudaGetSymbolAddress((void**)&mxh,  g_mxh);
    cudaGetSymbolAddress((void**)&mxl,  g_mxl);
    cudaGetSymbolAddress((void**)&gxh,  g_gxh);
    cudaGetSymbolAddress((void**)&gxl,  g_gxl);
    cudaGetSymbolAddress((void**)&aggh, g_aggh);
    cudaGetSymbolAddress((void**)&aggl, g_aggl);
    cudaGetSymbolAddress((void**)&aggf, g_agg);

    __half* wh_e1 = wh;                  __half* wl_e1 = wl;
    __half* wh_e2 = wh + 256 * 512;      __half* wl_e2 = wl + 256 * 512;
    __half* wh_g1 = wh_e2 + 256 * 256;   __half* wl_g1 = wl_e2 + 256 * 256;
    __half* wh_g2 = wh_g1 + 256 * 512;   __half* wl_g2 = wl_g1 + 256 * 512;

    static bool attr_set = false;
    if (!attr_set) {
        cudaFuncSetAttribute(mma_gemm<0,512>, cudaFuncAttributeMaxDynamicSharedMemorySize, SMEM_SZ);
        cudaFuncSetAttribute(mma_gemm<1,256>, cudaFuncAttributeMaxDynamicSharedMemorySize, SMEM_SZ);
        cudaFuncSetAttribute(mma_gemm<2,512>, cudaFuncAttributeMaxDynamicSharedMemorySize, SMEM_SZ);
        cudaFuncSetAttribute(mma_gemm<3,256>, cudaFuncAttributeMaxDynamicSharedMemorySize, SMEM_SZ);
        attr_set = true;
    }

    const int GE = (N_EDGE + 127) / 128;   // 2344
    const int GG = (N_GRID + 127) / 128;   // 782

    // launch order positions the big edge-L1 GEMM at slot 5 for the ncu window
    zero_agg_kernel<<<25000, 256>>>();                                             // 1
    split_kernel<<<(N_MESH * DH / 4 + 255) / 256, 256>>>(                          // 2
        (const float4*)mesh_x, (uint2*)mxh, (uint2*)mxl, N_MESH * DH / 4);
    split_kernel<<<(N_GRID * DH / 4 + 255) / 256, 256>>>(                          // 3
        (const float4*)grid_x, (uint2*)gxh, (uint2*)gxl, N_GRID * DH / 4);
    prep_w_kernel<<<dim3(8, 16), dim3(32, 8)>>>(w1_e, wh_e1, wl_e1, 512);          // 4
    mma_gemm<0,512><<<dim3(GE,2), 256, SMEM_SZ>>>(edge_src, edge_dst,              // 5
        wh_e1, wl_e1, b1_e, nullptr, nullptr, N_EDGE);
    prep_w_kernel<<<dim3(8,  8), dim3(32, 8)>>>(w2_e, wh_e2, wl_e2, 256);          // 6
    mma_gemm<1,256><<<dim3(GE,2), 256, SMEM_SZ>>>(nullptr, edge_dst,               // 7
        wh_e2, wl_e2, b2_e, nullptr, nullptr, N_EDGE);
    split_kernel<<<(N_GRID * DH / 4 + 255) / 256, 256>>>(                          // 8
        (const float4*)aggf, (uint2*)aggh, (uint2*)aggl, N_GRID * DH / 4);
    prep_w_kernel<<<dim3(8, 16), dim3(32, 8)>>>(w1_g, wh_g1, wl_g1, 512);          // 9
    mma_gemm<2,512><<<dim3(GG,2), 256, SMEM_SZ>>>(nullptr, nullptr,                // 10
        wh_g1, wl_g1, b1_g, nullptr, nullptr, N_GRID);
    prep_w_kernel<<<dim3(8,  8), dim3(32, 8)>>>(w2_g, wh_g2, wl_g2, 256);          // 11
    mma_gemm<3,256><<<dim3(GG,2), 256, SMEM_SZ>>>(nullptr, nullptr,                // 12
        wh_g2, wl_g2, b2_g, out, grid_x, N_GRID);
}

// round 5
// speedup vs baseline: 3.1798x; 1.4258x over previous
#include <cuda_runtime.h>
#include <cuda_fp16.h>
#include <cstdint>

#define N_MESH 10000
#define N_GRID 100000
#define N_EDGE 300000
#define DH     256

// ---------------- device scratch ----------------------------------------------
__device__ float g_agg[(size_t)N_GRID * DH];
__device__ float g_mproj[(size_t)N_MESH * DH];   // mesh_x @ W1e_top
__device__ float g_gproj[(size_t)N_GRID * DH];   // grid_x @ W1e_bot
__device__ __align__(16) __half g_mxh[(size_t)N_MESH * DH];
__device__ __align__(16) __half g_mxl[(size_t)N_MESH * DH];
__device__ __align__(16) __half g_gxh[(size_t)N_GRID * DH];
__device__ __align__(16) __half g_gxl[(size_t)N_GRID * DH];
__device__ __align__(16) __half g_aggh[(size_t)N_GRID * DH];
__device__ __align__(16) __half g_aggl[(size_t)N_GRID * DH];
__device__ __align__(16) __half g_H1h[(size_t)N_EDGE * DH];
__device__ __align__(16) __half g_H1l[(size_t)N_EDGE * DH];
__device__ __align__(16) __half g_H2h[(size_t)N_GRID * DH];
__device__ __align__(16) __half g_H2l[(size_t)N_GRID * DH];
__device__ __align__(16) __half g_Wh[(512 + 256 + 512 + 256) * DH];
__device__ __align__(16) __half g_Wl[(512 + 256 + 512 + 256) * DH];

// ---------------- helpers -------------------------------------------------------
__device__ __forceinline__ uint32_t smem_u32(const void* p) {
    uint32_t a;
    asm("{ .reg .u64 t; cvta.to.shared.u64 t, %1; cvt.u32.u64 %0, t; }"
        : "=r"(a) : "l"(p));
    return a;
}

#define LDSM_X4(r, addr)                                                     \
    asm volatile("ldmatrix.sync.aligned.m8n8.x4.shared.b16 {%0,%1,%2,%3}, [%4];" \
        : "=r"((r)[0]), "=r"((r)[1]), "=r"((r)[2]), "=r"((r)[3]) : "r"(addr))

#define MMA16816(c, a, b0, b1)                                               \
    asm volatile("mma.sync.aligned.m16n8k16.row.col.f32.f16.f16.f32 "        \
        "{%0,%1,%2,%3}, {%4,%5,%6,%7}, {%8,%9}, {%0,%1,%2,%3};"              \
        : "+f"((c)[0]), "+f"((c)[1]), "+f"((c)[2]), "+f"((c)[3])             \
        : "r"((a)[0]), "r"((a)[1]), "r"((a)[2]), "r"((a)[3]), "r"(b0), "r"(b1))

#define CP16(dst, src) \
    asm volatile("cp.async.cg.shared.global [%0], [%1], 16;" :: "r"(dst), "l"(src))
#define CP_COMMIT() asm volatile("cp.async.commit_group;")
#define CP_WAIT1()  asm volatile("cp.async.wait_group 1;")
#define CP_WAIT0()  asm volatile("cp.async.wait_group 0;")

__device__ __forceinline__ void red_add_v2(float* p, float x, float y) {
    asm volatile("red.global.add.v2.f32 [%0], {%1,%2};"
                 :: "l"(p), "f"(x), "f"(y) : "memory");
}

// ---------------- aux kernels ----------------------------------------------------
__global__ void zero_agg_kernel() {
    size_t i = ((size_t)blockIdx.x * blockDim.x + threadIdx.x) * 4;
    *(float4*)&g_agg[i] = make_float4(0.f, 0.f, 0.f, 0.f);
}

__global__ void split_kernel(const float4* __restrict__ in,
                             uint2* __restrict__ h, uint2* __restrict__ l, int n4) {
    int i = blockIdx.x * blockDim.x + threadIdx.x;
    if (i >= n4) return;
    float4 v = in[i];
    __half2 h01 = __floats2half2_rn(v.x, v.y);
    __half2 h23 = __floats2half2_rn(v.z, v.w);
    __half2 l01 = __floats2half2_rn(v.x - __low2float(h01), v.y - __high2float(h01));
    __half2 l23 = __floats2half2_rn(v.z - __low2float(h23), v.w - __high2float(h23));
    h[i] = make_uint2(*(uint32_t*)&h01, *(uint32_t*)&h23);
    l[i] = make_uint2(*(uint32_t*)&l01, *(uint32_t*)&l23);
}

// weights: in[k][256] fp32 -> outh/outl[n][K] fp16 (transpose + split)
__global__ void prep_w_kernel(const float* __restrict__ in,
                              __half* __restrict__ outh,
                              __half* __restrict__ outl, int K) {
    __shared__ float t[32][33];
    int bx = blockIdx.x * 32, by = blockIdx.y * 32;
    int tx = threadIdx.x, ty = threadIdx.y;
    #pragma unroll
    for (int i = 0; i < 32; i += 8)
        t[ty + i][tx] = in[(size_t)(by + ty + i) * DH + bx + tx];
    __syncthreads();
    #pragma unroll
    for (int i = 0; i < 32; i += 8) {
        float v = t[tx][ty + i];
        __half hh = __float2half_rn(v);
        __half ll = __float2half_rn(v - __half2float(hh));
        size_t o = (size_t)(bx + ty + i) * K + by + tx;
        outh[o] = hh;
        outl[o] = ll;
    }
}

// combine: H1 = split(relu(mproj[src[e]] + gproj[dst[e]] + b1)); one warp per edge
__global__ void combine_kernel(const int* __restrict__ isrc,
                               const int* __restrict__ idst,
                               const float* __restrict__ bias) {
    int e = blockIdx.x * 8 + (threadIdx.x >> 5);
    if (e >= N_EDGE) return;
    int lane = threadIdx.x & 31;
    const float4* mp = (const float4*)(g_mproj + (size_t)isrc[e] * DH);
    const float4* gp = (const float4*)(g_gproj + (size_t)idst[e] * DH);
    const float4* bp = (const float4*)bias;
    #pragma unroll
    for (int i = 0; i < 2; ++i) {
        int c = lane + i * 32;          // float4 index within row, 0..63
        float4 a = mp[c], b = gp[c], bb = bp[c];
        float x0 = fmaxf(a.x + b.x + bb.x, 0.f);
        float x1 = fmaxf(a.y + b.y + bb.y, 0.f);
        float x2 = fmaxf(a.z + b.z + bb.z, 0.f);
        float x3 = fmaxf(a.w + b.w + bb.w, 0.f);
        __half2 h01 = __floats2half2_rn(x0, x1);
        __half2 h23 = __floats2half2_rn(x2, x3);
        __half2 l01 = __floats2half2_rn(x0 - __low2float(h01), x1 - __high2float(h01));
        __half2 l23 = __floats2half2_rn(x2 - __low2float(h23), x3 - __high2float(h23));
        *(uint2*)&g_H1h[(size_t)e * DH + c * 4] = make_uint2(*(uint32_t*)&h01, *(uint32_t*)&h23);
        *(uint2*)&g_H1l[(size_t)e * DH + c * 4] = make_uint2(*(uint32_t*)&l01, *(uint32_t*)&l23);
    }
}

// ---------------- main GEMM -------------------------------------------------------
// C[M,256] = op(A[M,K] @ W + bias), fp16 3-term split via mma.sync.
// MODE 0 (proj):   A = Ah0/Al0, no bias, fp32 -> out.  (weight row stride ldw)
// MODE 1 (edgeL2): A = Ah0/Al0 (=H1), +bias, red.v2 scatter -> g_agg[idst]
// MODE 2 (gridL1): A = concat(Ah0/Al0, Ah1/Al1), K=512; relu -> H2 h/l split
// MODE 3 (gridL2): A = Ah0/Al0 (=H2), +bias +resid -> out
static constexpr int BK = 32;
static constexpr uint32_t RSTRIDE = 80;
static constexpr uint32_t MATB = 128 * RSTRIDE;
static constexpr uint32_t BUFB = 4 * MATB;
static constexpr uint32_t TILES = 2048;
static constexpr uint32_t SMEM_SZ = TILES + 2 * BUFB;   // 83968

template<int MODE, int K>
__global__ __launch_bounds__(256, 1)
void mma_gemm(const __half* __restrict__ Ah0, const __half* __restrict__ Al0,
              const __half* __restrict__ Ah1, const __half* __restrict__ Al1,
              const int*   __restrict__ idst,
              const __half* __restrict__ Wh, const __half* __restrict__ Wl,
              int ldw,
              const float* __restrict__ bias,
              float*       __restrict__ out,
              const float* __restrict__ resid,
              int M)
{
    extern __shared__ char smem[];
    constexpr int NCH = K / BK;
    const uint32_t sb = smem_u32(smem);

    const int tid  = threadIdx.x;
    const int wid  = tid >> 5;
    const int lane = tid & 31;
    const int m0 = blockIdx.x * 128;
    const int n0 = blockIdx.y * 128;

    float* s_bias = (float*)(smem);
    if (MODE != 0) s_bias[tid] = bias[tid];
    __syncthreads();

    auto load_chunk = [&](int buf, int kt) {
        const uint32_t ab = sb + TILES + (uint32_t)buf * BUFB;
        #pragma unroll
        for (int it = 0; it < 2; ++it) {
            int e = it * 256 + tid;
            int row = e >> 2;
            int cq = e & 3;
            int rr = m0 + row; if (rr >= M) rr = M - 1;
            const __half *ph, *pl;
            int kk;
            if (MODE == 2) {
                size_t r = (size_t)rr * DH;
                if (kt < DH) { ph = Ah0 + r; pl = Al0 + r; kk = kt; }
                else         { ph = Ah1 + r; pl = Al1 + r; kk = kt - DH; }
            } else {
                size_t r = (size_t)rr * DH;
                ph = Ah0 + r; pl = Al0 + r; kk = kt;
            }
            uint32_t off = (uint32_t)row * RSTRIDE + (uint32_t)cq * 16;
            CP16(ab + off,        ph + kk + cq * 8);
            CP16(ab + MATB + off, pl + kk + cq * 8);
        }
        #pragma unroll
        for (int it = 0; it < 2; ++it) {
            int e = it * 256 + tid;
            int row = e >> 2;
            int cq = e & 3;
            size_t g = (size_t)(n0 + row) * ldw + kt + cq * 8;
            uint32_t off = (uint32_t)row * RSTRIDE + (uint32_t)cq * 16;
            CP16(ab + 2 * MATB + off, Wh + g);
            CP16(ab + 3 * MATB + off, Wl + g);
        }
        CP_COMMIT();
    };

    const int wm = wid & 3;
    const int wn = wid >> 2;

    float acc[2][8][4];
    #pragma unroll
    for (int i = 0; i < 2; ++i)
        #pragma unroll
        for (int j = 0; j < 8; ++j)
            #pragma unroll
            for (int q = 0; q < 4; ++q)
                acc[i][j][q] = 0.f;

    load_chunk(0, 0);

    for (int c = 0; c < NCH; ++c) {
        int buf = c & 1;
        if (c + 1 < NCH) { load_chunk(buf ^ 1, (c + 1) * BK); CP_WAIT1(); }
        else             { CP_WAIT0(); }
        __syncthreads();

        const uint32_t tb = sb + TILES + (uint32_t)buf * BUFB;
        const uint32_t a_base = tb + (uint32_t)(wm * 32 + (lane & 15)) * RSTRIDE
                                   + (uint32_t)((lane >> 4) * 16);
        const uint32_t b_base = tb + 2 * MATB
                                   + (uint32_t)(wn * 64 + ((lane >> 4) & 1) * 8 + (lane & 7)) * RSTRIDE
                                   + (uint32_t)(((lane >> 3) & 1) * 16);
        #pragma unroll
        for (int s = 0; s < 2; ++s) {
            uint32_t ah[2][4], al[2][4];
            LDSM_X4(ah[0], a_base + s * 32);
            LDSM_X4(ah[1], a_base + 16 * RSTRIDE + s * 32);
            LDSM_X4(al[0], a_base + MATB + s * 32);
            LDSM_X4(al[1], a_base + MATB + 16 * RSTRIDE + s * 32);
            #pragma unroll
            for (int p = 0; p < 4; ++p) {
                uint32_t bh[4], bl[4];
                LDSM_X4(bh, b_base + (uint32_t)(p * 16) * RSTRIDE + s * 32);
                LDSM_X4(bl, b_base + MATB + (uint32_t)(p * 16) * RSTRIDE + s * 32);
                MMA16816(acc[0][2*p],   ah[0], bh[0], bh[1]);
                MMA16816(acc[1][2*p],   ah[1], bh[0], bh[1]);
                MMA16816(acc[0][2*p+1], ah[0], bh[2], bh[3]);
                MMA16816(acc[1][2*p+1], ah[1], bh[2], bh[3]);
                MMA16816(acc[0][2*p],   al[0], bh[0], bh[1]);
                MMA16816(acc[1][2*p],   al[1], bh[0], bh[1]);
                MMA16816(acc[0][2*p+1], al[0], bh[2], bh[3]);
                MMA16816(acc[1][2*p+1], al[1], bh[2], bh[3]);
                MMA16816(acc[0][2*p],   ah[0], bl[0], bl[1]);
                MMA16816(acc[1][2*p],   ah[1], bl[0], bl[1]);
                MMA16816(acc[0][2*p+1], ah[0], bl[2], bl[3]);
                MMA16816(acc[1][2*p+1], ah[1], bl[2], bl[3]);
            }
        }
        __syncthreads();
    }

    // ---- epilogue ----
    #pragma unroll
    for (int mt = 0; mt < 2; ++mt) {
        #pragma unroll
        for (int nt = 0; nt < 8; ++nt) {
            int r0  = m0 + wm * 32 + mt * 16 + (lane >> 2);
            int r1  = r0 + 8;
            int col = n0 + (wn * 64 + (nt >> 1) * 16 + (nt & 1) * 8) + (lane & 3) * 2;
            float b0 = (MODE != 0) ? s_bias[col & 255] : 0.f;
            float b1 = (MODE != 0) ? s_bias[(col + 1) & 255] : 0.f;
            float v00 = acc[mt][nt][0] + b0, v01 = acc[mt][nt][1] + b1;
            float v10 = acc[mt][nt][2] + b0, v11 = acc[mt][nt][3] + b1;
            if (MODE == 0) {
                if (r0 < M) *(float2*)&out[(size_t)r0 * DH + col] = make_float2(v00, v01);
                if (r1 < M) *(float2*)&out[(size_t)r1 * DH + col] = make_float2(v10, v11);
            } else if (MODE == 2) {
                if (r0 < M) {
                    float a = fmaxf(v00, 0.f), b = fmaxf(v01, 0.f);
                    __half2 hh = __floats2half2_rn(a, b);
                    __half2 ll = __floats2half2_rn(a - __low2float(hh), b - __high2float(hh));
                    *(__half2*)&g_H2h[(size_t)r0 * DH + col] = hh;
                    *(__half2*)&g_H2l[(size_t)r0 * DH + col] = ll;
                }
                if (r1 < M) {
                    float a = fmaxf(v10, 0.f), b = fmaxf(v11, 0.f);
                    __half2 hh = __floats2half2_rn(a, b);
                    __half2 ll = __floats2half2_rn(a - __low2float(hh), b - __high2float(hh));
                    *(__half2*)&g_H2h[(size_t)r1 * DH + col] = hh;
                    *(__half2*)&g_H2l[(size_t)r1 * DH + col] = ll;
                }
            } else if (MODE == 1) {
                if (r0 < M) red_add_v2(&g_agg[(size_t)idst[r0] * DH + col], v00, v01);
                if (r1 < M) red_add_v2(&g_agg[(size_t)idst[r1] * DH + col], v10, v11);
            } else {
                if (r0 < M) {
                    float2 rv = *(const float2*)&resid[(size_t)r0 * DH + col];
                    *(float2*)&out[(size_t)r0 * DH + col] = make_float2(v00 + rv.x, v01 + rv.y);
                }
                if (r1 < M) {
                    float2 rv = *(const float2*)&resid[(size_t)r1 * DH + col];
                    *(float2*)&out[(size_t)r1 * DH + col] = make_float2(v10 + rv.x, v11 + rv.y);
                }
            }
        }
    }
}

// ---------------- launch -----------------------------------------------------------
extern "C" void kernel_launch(void* const* d_in, const int* in_sizes, int n_in,
                              void* d_out, int out_size) {
    const float* mesh_x   = (const float*)d_in[0];
    const float* grid_x   = (const float*)d_in[1];
    const int*   edge_src = (const int*)  d_in[2];
    const int*   edge_dst = (const int*)  d_in[3];
    const float* w1_e = (const float*)d_in[4];
    const float* b1_e = (const float*)d_in[5];
    const float* w2_e = (const float*)d_in[6];
    const float* b2_e = (const float*)d_in[7];
    const float* w1_g = (const float*)d_in[8];
    const float* b1_g = (const float*)d_in[9];
    const float* w2_g = (const float*)d_in[10];
    const float* b2_g = (const float*)d_in[11];
    float* out = (float*)d_out;

    __half *wh, *wl, *mxh, *mxl, *gxh, *gxl, *aggh, *aggl;
    __half *h1h, *h1l, *h2h, *h2l;
    float *aggf, *mproj, *gproj;
    cudaGetSymbolAddress((void**)&wh,    g_Wh);
    cudaGetSymbolAddress((void**)&wl,    g_Wl);
    cudaGetSymbolAddress((void**)&mxh,   g_mxh);
    cudaGetSymbolAddress((void**)&mxl,   g_mxl);
    cudaGetSymbolAddress((void**)&gxh,   g_gxh);
    cudaGetSymbolAddress((void**)&gxl,   g_gxl);
    cudaGetSymbolAddress((void**)&aggh,  g_aggh);
    cudaGetSymbolAddress((void**)&aggl,  g_aggl);
    cudaGetSymbolAddress((void**)&h1h,   g_H1h);
    cudaGetSymbolAddress((void**)&h1l,   g_H1l);
    cudaGetSymbolAddress((void**)&h2h,   g_H2h);
    cudaGetSymbolAddress((void**)&h2l,   g_H2l);
    cudaGetSymbolAddress((void**)&aggf,  g_agg);
    cudaGetSymbolAddress((void**)&mproj, g_mproj);
    cudaGetSymbolAddress((void**)&gproj, g_gproj);

    __half* wh_e1 = wh;                  __half* wl_e1 = wl;
    __half* wh_e2 = wh + 256 * 512;      __half* wl_e2 = wl + 256 * 512;
    __half* wh_g1 = wh_e2 + 256 * 256;   __half* wl_g1 = wl_e2 + 256 * 256;
    __half* wh_g2 = wh_g1 + 256 * 512;   __half* wl_g2 = wl_g1 + 256 * 512;

    static bool attr_set = false;
    if (!attr_set) {
        cudaFuncSetAttribute(mma_gemm<0,256>, cudaFuncAttributeMaxDynamicSharedMemorySize, SMEM_SZ);
        cudaFuncSetAttribute(mma_gemm<1,256>, cudaFuncAttributeMaxDynamicSharedMemorySize, SMEM_SZ);
        cudaFuncSetAttribute(mma_gemm<2,512>, cudaFuncAttributeMaxDynamicSharedMemorySize, SMEM_SZ);
        cudaFuncSetAttribute(mma_gemm<3,256>, cudaFuncAttributeMaxDynamicSharedMemorySize, SMEM_SZ);
        attr_set = true;
    }

    const int GM = (N_MESH + 127) / 128;   // 79
    const int GG = (N_GRID + 127) / 128;   // 782
    const int GE = (N_EDGE + 127) / 128;   // 2344

    // 1
    zero_agg_kernel<<<25000, 256>>>();
    // 2-3
    split_kernel<<<(N_MESH * DH / 4 + 255) / 256, 256>>>(
        (const float4*)mesh_x, (uint2*)mxh, (uint2*)mxl, N_MESH * DH / 4);
    split_kernel<<<(N_GRID * DH / 4 + 255) / 256, 256>>>(
        (const float4*)grid_x, (uint2*)gxh, (uint2*)gxl, N_GRID * DH / 4);
    // 4
    prep_w_kernel<<<dim3(8, 16), dim3(32, 8)>>>(w1_e, wh_e1, wl_e1, 512);
    // 5: mesh_proj = mesh_x @ W1e_top
    mma_gemm<0,256><<<dim3(GM,2), 256, SMEM_SZ>>>(mxh, mxl, nullptr, nullptr, nullptr,
        wh_e1, wl_e1, 512, nullptr, mproj, nullptr, N_MESH);
    // 6: grid_proj = grid_x @ W1e_bot   <- ncu capture slot
    mma_gemm<0,256><<<dim3(GG,2), 256, SMEM_SZ>>>(gxh, gxl, nullptr, nullptr, nullptr,
        wh_e1 + 256, wl_e1 + 256, 512, nullptr, gproj, nullptr, N_GRID);
    // 7: combine -> H1
    combine_kernel<<<(N_EDGE + 7) / 8, 256>>>(edge_src, edge_dst, b1_e);
    // 8
    prep_w_kernel<<<dim3(8,  8), dim3(32, 8)>>>(w2_e, wh_e2, wl_e2, 256);
    // 9: edge L2 + scatter
    mma_gemm<1,256><<<dim3(GE,2), 256, SMEM_SZ>>>(h1h, h1l, nullptr, nullptr, edge_dst,
        wh_e2, wl_e2, 256, b2_e, nullptr, nullptr, N_EDGE);
    // 10
    split_kernel<<<(N_GRID * DH / 4 + 255) / 256, 256>>>(
        (const float4*)aggf, (uint2*)aggh, (uint2*)aggl, N_GRID * DH / 4);
    // 11
    prep_w_kernel<<<dim3(8, 16), dim3(32, 8)>>>(w1_g, wh_g1, wl_g1, 512);
    // 12: grid L1
    mma_gemm<2,512><<<dim3(GG,2), 256, SMEM_SZ>>>(gxh, gxl, aggh, aggl, nullptr,
        wh_g1, wl_g1, 512, b1_g, nullptr, nullptr, N_GRID);
    // 13
    prep_w_kernel<<<dim3(8,  8), dim3(32, 8)>>>(w2_g, wh_g2, wl_g2, 256);
    // 14: grid L2 + residual
    mma_gemm<3,256><<<dim3(GG,2), 256, SMEM_SZ>>>(h2h, h2l, nullptr, nullptr, nullptr,
        wh_g2, wl_g2, 256, b2_g, out, grid_x, N_GRID);
}

// round 6
// speedup vs baseline: 4.7950x; 1.5080x over previous
#include <cuda_runtime.h>
#include <cuda_fp16.h>
#include <cstdint>

#define N_MESH 10000
#define N_GRID 100000
#define N_EDGE 300000
#define DH     256

// ---------------- device scratch ----------------------------------------------
__device__ float g_agg[(size_t)N_GRID * DH];     // aggH1 = segment_sum(H1)
__device__ float g_deg[N_GRID];                  // edge count per grid node
__device__ float g_cvec[DH];                     // b2e @ W1g_bot
__device__ float g_mproj[(size_t)N_MESH * DH];   // mesh_x @ W1e_top
__device__ float g_gproj[(size_t)N_GRID * DH];   // grid_x @ W1e_bot
__device__ __align__(16) __half g_mxh[(size_t)N_MESH * DH];
__device__ __align__(16) __half g_mxl[(size_t)N_MESH * DH];
__device__ __align__(16) __half g_gxh[(size_t)N_GRID * DH];
__device__ __align__(16) __half g_gxl[(size_t)N_GRID * DH];
__device__ __align__(16) __half g_aggh[(size_t)N_GRID * DH];
__device__ __align__(16) __half g_aggl[(size_t)N_GRID * DH];
__device__ __align__(16) __half g_H2h[(size_t)N_GRID * DH];
__device__ __align__(16) __half g_H2l[(size_t)N_GRID * DH];
// weight arena: [0) W1e_T (256x512) | [256*512) Wcat (256x512) | [2*256*512) W2g_T (256x256)
__device__ __align__(16) __half g_Wh[2 * 256 * 512 + 256 * 256];
__device__ __align__(16) __half g_Wl[2 * 256 * 512 + 256 * 256];

// ---------------- helpers -------------------------------------------------------
__device__ __forceinline__ uint32_t smem_u32(const void* p) {
    uint32_t a;
    asm("{ .reg .u64 t; cvta.to.shared.u64 t, %1; cvt.u32.u64 %0, t; }"
        : "=r"(a) : "l"(p));
    return a;
}

#define LDSM_X4(r, addr)                                                     \
    asm volatile("ldmatrix.sync.aligned.m8n8.x4.shared.b16 {%0,%1,%2,%3}, [%4];" \
        : "=r"((r)[0]), "=r"((r)[1]), "=r"((r)[2]), "=r"((r)[3]) : "r"(addr))

#define MMA16816(c, a, b0, b1)                                               \
    asm volatile("mma.sync.aligned.m16n8k16.row.col.f32.f16.f16.f32 "        \
        "{%0,%1,%2,%3}, {%4,%5,%6,%7}, {%8,%9}, {%0,%1,%2,%3};"              \
        : "+f"((c)[0]), "+f"((c)[1]), "+f"((c)[2]), "+f"((c)[3])             \
        : "r"((a)[0]), "r"((a)[1]), "r"((a)[2]), "r"((a)[3]), "r"(b0), "r"(b1))

#define CP16(dst, src) \
    asm volatile("cp.async.cg.shared.global [%0], [%1], 16;" :: "r"(dst), "l"(src))
#define CP_COMMIT() asm volatile("cp.async.commit_group;")
#define CP_WAIT1()  asm volatile("cp.async.wait_group 1;")
#define CP_WAIT0()  asm volatile("cp.async.wait_group 0;")

__device__ __forceinline__ void red_add_v4(float* p, float4 v) {
    asm volatile("red.global.add.v4.f32 [%0], {%1,%2,%3,%4};"
                 :: "l"(p), "f"(v.x), "f"(v.y), "f"(v.z), "f"(v.w) : "memory");
}
__device__ __forceinline__ void red_add_f32(float* p, float v) {
    asm volatile("red.global.add.f32 [%0], %1;" :: "l"(p), "f"(v) : "memory");
}

// ---------------- aux kernels ----------------------------------------------------
__global__ void zero_agg_kernel() {
    size_t i = ((size_t)blockIdx.x * blockDim.x + threadIdx.x) * 4;
    *(float4*)&g_agg[i] = make_float4(0.f, 0.f, 0.f, 0.f);
}
__global__ void zero_deg_kernel() {
    int i = blockIdx.x * blockDim.x + threadIdx.x;
    if (i < N_GRID) g_deg[i] = 0.f;
}

__global__ void split_kernel(const float4* __restrict__ in,
                             uint2* __restrict__ h, uint2* __restrict__ l, int n4) {
    int i = blockIdx.x * blockDim.x + threadIdx.x;
    if (i >= n4) return;
    float4 v = in[i];
    __half2 h01 = __floats2half2_rn(v.x, v.y);
    __half2 h23 = __floats2half2_rn(v.z, v.w);
    __half2 l01 = __floats2half2_rn(v.x - __low2float(h01), v.y - __high2float(h01));
    __half2 l23 = __floats2half2_rn(v.z - __low2float(h23), v.w - __high2float(h23));
    h[i] = make_uint2(*(uint32_t*)&h01, *(uint32_t*)&h23);
    l[i] = make_uint2(*(uint32_t*)&l01, *(uint32_t*)&l23);
}

// weights: in[k][256] fp32 -> outh/outl[n][K] fp16 (transpose + split); covers
// k-range = 32*gridDim.y rows starting at row 0.
__global__ void prep_w_kernel(const float* __restrict__ in,
                              __half* __restrict__ outh,
                              __half* __restrict__ outl, int K) {
    __shared__ float t[32][33];
    int bx = blockIdx.x * 32, by = blockIdx.y * 32;
    int tx = threadIdx.x, ty = threadIdx.y;
    #pragma unroll
    for (int i = 0; i < 32; i += 8)
        t[ty + i][tx] = in[(size_t)(by + ty + i) * DH + bx + tx];
    __syncthreads();
    #pragma unroll
    for (int i = 0; i < 32; i += 8) {
        float v = t[tx][ty + i];
        __half hh = __float2half_rn(v);
        __half ll = __float2half_rn(v - __half2float(hh));
        size_t o = (size_t)(bx + ty + i) * K + by + tx;
        outh[o] = hh;
        outl[o] = ll;
    }
}

// Wfused = W2e @ W1g_bot, written transposed+split into Wcat columns 256..511.
// block = k (0..255), thread = n (0..255).
__global__ void fuse_w_kernel(const float* __restrict__ w2e,
                              const float* __restrict__ w1g,
                              __half* __restrict__ outh, __half* __restrict__ outl) {
    int k = blockIdx.x, n = threadIdx.x;
    float acc = 0.f;
    for (int j = 0; j < DH; ++j)
        acc = fmaf(w2e[k * DH + j], w1g[(size_t)(DH + j) * DH + n], acc);
    __half hh = __float2half_rn(acc);
    __half ll = __float2half_rn(acc - __half2float(hh));
    outh[(size_t)n * 512 + 256 + k] = hh;
    outl[(size_t)n * 512 + 256 + k] = ll;
}

// cvec = b2e @ W1g_bot
__global__ void cvec_kernel(const float* __restrict__ b2e, const float* __restrict__ w1g) {
    int n = threadIdx.x;
    float acc = 0.f;
    for (int j = 0; j < DH; ++j)
        acc = fmaf(b2e[j], w1g[(size_t)(DH + j) * DH + n], acc);
    g_cvec[n] = acc;
}

// combine+scatter: per edge e (one warp):
//   h1 = relu(mproj[src] + gproj[dst] + b1e);  aggH1[dst] += h1;  deg[dst] += 1
__global__ void combine_kernel(const int* __restrict__ isrc,
                               const int* __restrict__ idst,
                               const float* __restrict__ bias) {
    int e = blockIdx.x * 8 + (threadIdx.x >> 5);
    if (e >= N_EDGE) return;
    int lane = threadIdx.x & 31;
    int s = isrc[e], d = idst[e];
    const float4* mp = (const float4*)(g_mproj + (size_t)s * DH);
    const float4* gp = (const float4*)(g_gproj + (size_t)d * DH);
    const float4* bp = (const float4*)bias;
    float* ap = g_agg + (size_t)d * DH;
    if (lane == 0) red_add_f32(&g_deg[d], 1.0f);
    #pragma unroll
    for (int i = 0; i < 2; ++i) {
        int c = lane + i * 32;
        float4 a = mp[c], b = gp[c], bb = bp[c];
        float4 v;
        v.x = fmaxf(a.x + b.x + bb.x, 0.f);
        v.y = fmaxf(a.y + b.y + bb.y, 0.f);
        v.z = fmaxf(a.z + b.z + bb.z, 0.f);
        v.w = fmaxf(a.w + b.w + bb.w, 0.f);
        red_add_v4(ap + c * 4, v);
    }
}

// ---------------- main GEMM -------------------------------------------------------
// MODE 0: C = A@W, fp32 -> out (projections)
// MODE 2: A = concat(Ah0,Ah1) K=512; epi = relu(acc + b1g + deg*cvec); split -> H2
// MODE 3: A = Ah0 K=256; epi = acc + bias + resid -> out
static constexpr int BK = 32;
static constexpr uint32_t RSTRIDE = 80;
static constexpr uint32_t MATB = 128 * RSTRIDE;
static constexpr uint32_t BUFB = 4 * MATB;
static constexpr uint32_t TILES = 2048;
static constexpr uint32_t SMEM_SZ = TILES + 2 * BUFB;   // 83968

template<int MODE, int K>
__global__ __launch_bounds__(256, 1)
void mma_gemm(const __half* __restrict__ Ah0, const __half* __restrict__ Al0,
              const __half* __restrict__ Ah1, const __half* __restrict__ Al1,
              const __half* __restrict__ Wh, const __half* __restrict__ Wl,
              int ldw,
              const float* __restrict__ bias,
              float*       __restrict__ out,
              const float* __restrict__ resid,   // grid_x (M3)
              int M)
{
    extern __shared__ char smem[];
    constexpr int NCH = K / BK;
    const uint32_t sb = smem_u32(smem);

    const int tid  = threadIdx.x;
    const int wid  = tid >> 5;
    const int lane = tid & 31;
    const int m0 = blockIdx.x * 128;
    const int n0 = blockIdx.y * 128;

    float* s_bias = (float*)(smem);          // 256 floats
    float* s_cvec = (float*)(smem + 1024);   // 256 floats (MODE 2)
    if (MODE != 0) s_bias[tid] = bias[tid];
    if (MODE == 2) s_cvec[tid] = g_cvec[tid & 255];
    __syncthreads();

    auto load_chunk = [&](int buf, int kt) {
        const uint32_t ab = sb + TILES + (uint32_t)buf * BUFB;
        #pragma unroll
        for (int it = 0; it < 2; ++it) {
            int e = it * 256 + tid;
            int row = e >> 2;
            int cq = e & 3;
            int rr = m0 + row; if (rr >= M) rr = M - 1;
            const __half *ph, *pl;
            int kk;
            if (MODE == 2) {
                size_t r = (size_t)rr * DH;
                if (kt < DH) { ph = Ah0 + r; pl = Al0 + r; kk = kt; }
                else         { ph = Ah1 + r; pl = Al1 + r; kk = kt - DH; }
            } else {
                size_t r = (size_t)rr * DH;
                ph = Ah0 + r; pl = Al0 + r; kk = kt;
            }
            uint32_t off = (uint32_t)row * RSTRIDE + (uint32_t)cq * 16;
            CP16(ab + off,        ph + kk + cq * 8);
            CP16(ab + MATB + off, pl + kk + cq * 8);
        }
        #pragma unroll
        for (int it = 0; it < 2; ++it) {
            int e = it * 256 + tid;
            int row = e >> 2;
            int cq = e & 3;
            size_t g = (size_t)(n0 + row) * ldw + kt + cq * 8;
            uint32_t off = (uint32_t)row * RSTRIDE + (uint32_t)cq * 16;
            CP16(ab + 2 * MATB + off, Wh + g);
            CP16(ab + 3 * MATB + off, Wl + g);
        }
        CP_COMMIT();
    };

    const int wm = wid & 3;
    const int wn = wid >> 2;

    float acc[2][8][4];
    #pragma unroll
    for (int i = 0; i < 2; ++i)
        #pragma unroll
        for (int j = 0; j < 8; ++j)
            #pragma unroll
            for (int q = 0; q < 4; ++q)
                acc[i][j][q] = 0.f;

    load_chunk(0, 0);

    for (int c = 0; c < NCH; ++c) {
        int buf = c & 1;
        if (c + 1 < NCH) { load_chunk(buf ^ 1, (c + 1) * BK); CP_WAIT1(); }
        else             { CP_WAIT0(); }
        __syncthreads();

        const uint32_t tb = sb + TILES + (uint32_t)buf * BUFB;
        const uint32_t a_base = tb + (uint32_t)(wm * 32 + (lane & 15)) * RSTRIDE
                                   + (uint32_t)((lane >> 4) * 16);
        const uint32_t b_base = tb + 2 * MATB
                                   + (uint32_t)(wn * 64 + ((lane >> 4) & 1) * 8 + (lane & 7)) * RSTRIDE
                                   + (uint32_t)(((lane >> 3) & 1) * 16);
        #pragma unroll
        for (int s = 0; s < 2; ++s) {
            uint32_t ah[2][4], al[2][4];
            LDSM_X4(ah[0], a_base + s * 32);
            LDSM_X4(ah[1], a_base + 16 * RSTRIDE + s * 32);
            LDSM_X4(al[0], a_base + MATB + s * 32);
            LDSM_X4(al[1], a_base + MATB + 16 * RSTRIDE + s * 32);
            #pragma unroll
            for (int p = 0; p < 4; ++p) {
                uint32_t bh[4], bl[4];
                LDSM_X4(bh, b_base + (uint32_t)(p * 16) * RSTRIDE + s * 32);
                LDSM_X4(bl, b_base + MATB + (uint32_t)(p * 16) * RSTRIDE + s * 32);
                MMA16816(acc[0][2*p],   ah[0], bh[0], bh[1]);
                MMA16816(acc[1][2*p],   ah[1], bh[0], bh[1]);
                MMA16816(acc[0][2*p+1], ah[0], bh[2], bh[3]);
                MMA16816(acc[1][2*p+1], ah[1], bh[2], bh[3]);
                MMA16816(acc[0][2*p],   al[0], bh[0], bh[1]);
                MMA16816(acc[1][2*p],   al[1], bh[0], bh[1]);
                MMA16816(acc[0][2*p+1], al[0], bh[2], bh[3]);
                MMA16816(acc[1][2*p+1], al[1], bh[2], bh[3]);
                MMA16816(acc[0][2*p],   ah[0], bl[0], bl[1]);
                MMA16816(acc[1][2*p],   ah[1], bl[0], bl[1]);
                MMA16816(acc[0][2*p+1], ah[0], bl[2], bl[3]);
                MMA16816(acc[1][2*p+1], ah[1], bl[2], bl[3]);
            }
        }
        __syncthreads();
    }

    // ---- epilogue ----
    #pragma unroll
    for (int mt = 0; mt < 2; ++mt) {
        int r0 = m0 + wm * 32 + mt * 16 + (lane >> 2);
        int r1 = r0 + 8;
        float d0 = 0.f, d1 = 0.f;
        if (MODE == 2) {
            if (r0 < M) d0 = g_deg[r0];
            if (r1 < M) d1 = g_deg[r1];
        }
        #pragma unroll
        for (int nt = 0; nt < 8; ++nt) {
            int col = n0 + (wn * 64 + (nt >> 1) * 16 + (nt & 1) * 8) + (lane & 3) * 2;
            float b0 = (MODE != 0) ? s_bias[col & 255] : 0.f;
            float b1 = (MODE != 0) ? s_bias[(col + 1) & 255] : 0.f;
            float v00 = acc[mt][nt][0] + b0, v01 = acc[mt][nt][1] + b1;
            float v10 = acc[mt][nt][2] + b0, v11 = acc[mt][nt][3] + b1;
            if (MODE == 0) {
                if (r0 < M) *(float2*)&out[(size_t)r0 * DH + col] = make_float2(v00, v01);
                if (r1 < M) *(float2*)&out[(size_t)r1 * DH + col] = make_float2(v10, v11);
            } else if (MODE == 2) {
                float c0 = s_cvec[col & 255], c1 = s_cvec[(col + 1) & 255];
                if (r0 < M) {
                    float a = fmaxf(v00 + d0 * c0, 0.f), b = fmaxf(v01 + d0 * c1, 0.f);
                    __half2 hh = __floats2half2_rn(a, b);
                    __half2 ll = __floats2half2_rn(a - __low2float(hh), b - __high2float(hh));
                    *(__half2*)&g_H2h[(size_t)r0 * DH + col] = hh;
                    *(__half2*)&g_H2l[(size_t)r0 * DH + col] = ll;
                }
                if (r1 < M) {
                    float a = fmaxf(v10 + d1 * c0, 0.f), b = fmaxf(v11 + d1 * c1, 0.f);
                    __half2 hh = __floats2half2_rn(a, b);
                    __half2 ll = __floats2half2_rn(a - __low2float(hh), b - __high2float(hh));
                    *(__half2*)&g_H2h[(size_t)r1 * DH + col] = hh;
                    *(__half2*)&g_H2l[(size_t)r1 * DH + col] = ll;
                }
            } else {
                if (r0 < M) {
                    float2 rv = *(const float2*)&resid[(size_t)r0 * DH + col];
                    *(float2*)&out[(size_t)r0 * DH + col] = make_float2(v00 + rv.x, v01 + rv.y);
                }
                if (r1 < M) {
                    float2 rv = *(const float2*)&resid[(size_t)r1 * DH + col];
                    *(float2*)&out[(size_t)r1 * DH + col] = make_float2(v10 + rv.x, v11 + rv.y);
                }
            }
        }
    }
}

// ---------------- launch -----------------------------------------------------------
extern "C" void kernel_launch(void* const* d_in, const int* in_sizes, int n_in,
                              void* d_out, int out_size) {
    const float* mesh_x   = (const float*)d_in[0];
    const float* grid_x   = (const float*)d_in[1];
    const int*   edge_src = (const int*)  d_in[2];
    const int*   edge_dst = (const int*)  d_in[3];
    const float* w1_e = (const float*)d_in[4];
    const float* b1_e = (const float*)d_in[5];
    const float* w2_e = (const float*)d_in[6];
    const float* b2_e = (const float*)d_in[7];
    const float* w1_g = (const float*)d_in[8];
    const float* b1_g = (const float*)d_in[9];
    const float* w2_g = (const float*)d_in[10];
    const float* b2_g = (const float*)d_in[11];
    float* out = (float*)d_out;

    __half *wh, *wl, *mxh, *mxl, *gxh, *gxl, *aggh, *aggl, *h2h, *h2l;
    float *aggf, *mproj, *gproj;
    cudaGetSymbolAddress((void**)&wh,    g_Wh);
    cudaGetSymbolAddress((void**)&wl,    g_Wl);
    cudaGetSymbolAddress((void**)&mxh,   g_mxh);
    cudaGetSymbolAddress((void**)&mxl,   g_mxl);
    cudaGetSymbolAddress((void**)&gxh,   g_gxh);
    cudaGetSymbolAddress((void**)&gxl,   g_gxl);
    cudaGetSymbolAddress((void**)&aggh,  g_aggh);
    cudaGetSymbolAddress((void**)&aggl,  g_aggl);
    cudaGetSymbolAddress((void**)&h2h,   g_H2h);
    cudaGetSymbolAddress((void**)&h2l,   g_H2l);
    cudaGetSymbolAddress((void**)&aggf,  g_agg);
    cudaGetSymbolAddress((void**)&mproj, g_mproj);
    cudaGetSymbolAddress((void**)&gproj, g_gproj);

    __half* wh_e1  = wh;                    __half* wl_e1  = wl;                  // W1e_T [256][512]
    __half* wh_cat = wh + 256 * 512;        __half* wl_cat = wl + 256 * 512;      // [W1g_top ; Wfused]_T
    __half* wh_g2  = wh + 2 * 256 * 512;    __half* wl_g2  = wl + 2 * 256 * 512;  // W2g_T [256][256]

    static bool attr_set = false;
    if (!attr_set) {
        cudaFuncSetAttribute(mma_gemm<0,256>, cudaFuncAttributeMaxDynamicSharedMemorySize, SMEM_SZ);
        cudaFuncSetAttribute(mma_gemm<2,512>, cudaFuncAttributeMaxDynamicSharedMemorySize, SMEM_SZ);
        cudaFuncSetAttribute(mma_gemm<3,256>, cudaFuncAttributeMaxDynamicSharedMemorySize, SMEM_SZ);
        attr_set = true;
    }

    const int GM = (N_MESH + 127) / 128;   // 79
    const int GG = (N_GRID + 127) / 128;   // 782

    // harness issues ~2 launches before ours; ncu capture = our launch #4
    // 1
    zero_agg_kernel<<<25000, 256>>>();
    // 2
    split_kernel<<<(N_GRID * DH / 4 + 255) / 256, 256>>>(
        (const float4*)grid_x, (uint2*)gxh, (uint2*)gxl, N_GRID * DH / 4);
    // 3
    prep_w_kernel<<<dim3(8, 16), dim3(32, 8)>>>(w1_e, wh_e1, wl_e1, 512);
    // 4: grid_proj = grid_x @ W1e_bot   <-- ncu capture
    mma_gemm<0,256><<<dim3(GG,2), 256, SMEM_SZ>>>(gxh, gxl, nullptr, nullptr,
        wh_e1 + 256, wl_e1 + 256, 512, nullptr, gproj, nullptr, N_GRID);
    // 5
    split_kernel<<<(N_MESH * DH / 4 + 255) / 256, 256>>>(
        (const float4*)mesh_x, (uint2*)mxh, (uint2*)mxl, N_MESH * DH / 4);
    // 6: mesh_proj = mesh_x @ W1e_top
    mma_gemm<0,256><<<dim3(GM,2), 256, SMEM_SZ>>>(mxh, mxl, nullptr, nullptr,
        wh_e1, wl_e1, 512, nullptr, mproj, nullptr, N_MESH);
    // 7
    zero_deg_kernel<<<(N_GRID + 255) / 256, 256>>>();
    // 8: combine + scatter H1 into aggH1, count deg
    combine_kernel<<<N_EDGE / 8, 256>>>(edge_src, edge_dst, b1_e);
    // 9: split aggH1
    split_kernel<<<(N_GRID * DH / 4 + 255) / 256, 256>>>(
        (const float4*)aggf, (uint2*)aggh, (uint2*)aggl, N_GRID * DH / 4);
    // 10: W1g_top transposed into Wcat cols 0..255
    prep_w_kernel<<<dim3(8, 8), dim3(32, 8)>>>(w1_g, wh_cat, wl_cat, 512);
    // 11: Wfused = W2e @ W1g_bot into Wcat cols 256..511
    fuse_w_kernel<<<256, 256>>>(w2_e, w1_g, wh_cat, wl_cat);
    // 12: cvec = b2e @ W1g_bot
    cvec_kernel<<<1, 256>>>(b2_e, w1_g);
    // 13: grid L1 (fused): relu(gx@W1g_top + aggH1@Wfused + deg*cvec + b1g) -> H2
    mma_gemm<2,512><<<dim3(GG,2), 256, SMEM_SZ>>>(gxh, gxl, aggh, aggl,
        wh_cat, wl_cat, 512, b1_g, nullptr, nullptr, N_GRID);
    // 14
    prep_w_kernel<<<dim3(8, 8), dim3(32, 8)>>>(w2_g, wh_g2, wl_g2, 256);
    // 15: grid L2 + residual
    mma_gemm<3,256><<<dim3(GG,2), 256, SMEM_SZ>>>(h2h, h2l, nullptr, nullptr,
        wh_g2, wl_g2, 256, b2_g, out, grid_x, N_GRID);
}

// round 7
// speedup vs baseline: 5.5193x; 1.1511x over previous
#include <cuda_runtime.h>
#include <cuda_fp16.h>
#include <cstdint>

#define N_MESH 10000
#define N_GRID 100000
#define N_EDGE 300000
#define DH     256

// ---------------- device scratch ----------------------------------------------
__device__ float g_agg[(size_t)N_GRID * DH];     // aggH1 = segment_sum(H1)
__device__ float g_deg[N_GRID];                  // edge count per grid node
__device__ float g_cvec[DH];                     // b2e @ W1g_bot
__device__ float g_mproj[(size_t)N_MESH * DH];   // mesh_x @ W1e_top
__device__ float g_gproj[(size_t)N_GRID * DH];   // grid_x @ W1e_bot
__device__ __align__(16) __half g_mxh[(size_t)N_MESH * DH];
__device__ __align__(16) __half g_mxl[(size_t)N_MESH * DH];
__device__ __align__(16) __half g_gxh[(size_t)N_GRID * DH];
__device__ __align__(16) __half g_gxl[(size_t)N_GRID * DH];
__device__ __align__(16) __half g_aggh[(size_t)N_GRID * DH];
__device__ __align__(16) __half g_aggl[(size_t)N_GRID * DH];
__device__ __align__(16) __half g_H2h[(size_t)N_GRID * DH];
__device__ __align__(16) __half g_H2l[(size_t)N_GRID * DH];
// weight arena: [0) W1e_T (256x512) | [256*512) Wcat (256x512) | [2*256*512) W2g_T (256x256)
__device__ __align__(16) __half g_Wh[2 * 256 * 512 + 256 * 256];
__device__ __align__(16) __half g_Wl[2 * 256 * 512 + 256 * 256];

// ---------------- helpers -------------------------------------------------------
__device__ __forceinline__ uint32_t smem_u32(const void* p) {
    uint32_t a;
    asm("{ .reg .u64 t; cvta.to.shared.u64 t, %1; cvt.u32.u64 %0, t; }"
        : "=r"(a) : "l"(p));
    return a;
}

#define LDSM_X4(r, addr)                                                     \
    asm volatile("ldmatrix.sync.aligned.m8n8.x4.shared.b16 {%0,%1,%2,%3}, [%4];" \
        : "=r"((r)[0]), "=r"((r)[1]), "=r"((r)[2]), "=r"((r)[3]) : "r"(addr))

#define MMA16816(c, a, b0, b1)                                               \
    asm volatile("mma.sync.aligned.m16n8k16.row.col.f32.f16.f16.f32 "        \
        "{%0,%1,%2,%3}, {%4,%5,%6,%7}, {%8,%9}, {%0,%1,%2,%3};"              \
        : "+f"((c)[0]), "+f"((c)[1]), "+f"((c)[2]), "+f"((c)[3])             \
        : "r"((a)[0]), "r"((a)[1]), "r"((a)[2]), "r"((a)[3]), "r"(b0), "r"(b1))

#define CP16(dst, src) \
    asm volatile("cp.async.cg.shared.global [%0], [%1], 16;" :: "r"(dst), "l"(src))
#define CP_COMMIT() asm volatile("cp.async.commit_group;")
#define CP_WAIT1()  asm volatile("cp.async.wait_group 1;")
#define CP_WAIT0()  asm volatile("cp.async.wait_group 0;")

__device__ __forceinline__ void red_add_v4(float* p, float4 v) {
    asm volatile("red.global.add.v4.f32 [%0], {%1,%2,%3,%4};"
                 :: "l"(p), "f"(v.x), "f"(v.y), "f"(v.z), "f"(v.w) : "memory");
}
__device__ __forceinline__ void red_add_f32(float* p, float v) {
    asm volatile("red.global.add.f32 [%0], %1;" :: "l"(p), "f"(v) : "memory");
}

// ---------------- aux kernels ----------------------------------------------------
// zero agg (25.6M floats) and deg (100k floats) in one kernel
__global__ void zero_kernel() {
    size_t i = ((size_t)blockIdx.x * blockDim.x + threadIdx.x) * 4;
    if (i < (size_t)N_GRID * DH)
        *(float4*)&g_agg[i] = make_float4(0.f, 0.f, 0.f, 0.f);
    if (i < N_GRID)
        *(float4*)&g_deg[i] = make_float4(0.f, 0.f, 0.f, 0.f);
}

__global__ void split_kernel(const float4* __restrict__ in,
                             uint2* __restrict__ h, uint2* __restrict__ l, int n4) {
    int i = blockIdx.x * blockDim.x + threadIdx.x;
    if (i >= n4) return;
    float4 v = in[i];
    __half2 h01 = __floats2half2_rn(v.x, v.y);
    __half2 h23 = __floats2half2_rn(v.z, v.w);
    __half2 l01 = __floats2half2_rn(v.x - __low2float(h01), v.y - __high2float(h01));
    __half2 l23 = __floats2half2_rn(v.z - __low2float(h23), v.w - __high2float(h23));
    h[i] = make_uint2(*(uint32_t*)&h01, *(uint32_t*)&h23);
    l[i] = make_uint2(*(uint32_t*)&l01, *(uint32_t*)&l23);
}

// weights: in[k][256] fp32 -> outh/outl[n][K] fp16 (transpose + split)
__global__ void prep_w_kernel(const float* __restrict__ in,
                              __half* __restrict__ outh,
                              __half* __restrict__ outl, int K) {
    __shared__ float t[32][33];
    int bx = blockIdx.x * 32, by = blockIdx.y * 32;
    int tx = threadIdx.x, ty = threadIdx.y;
    #pragma unroll
    for (int i = 0; i < 32; i += 8)
        t[ty + i][tx] = in[(size_t)(by + ty + i) * DH + bx + tx];
    __syncthreads();
    #pragma unroll
    for (int i = 0; i < 32; i += 8) {
        float v = t[tx][ty + i];
        __half hh = __float2half_rn(v);
        __half ll = __float2half_rn(v - __half2float(hh));
        size_t o = (size_t)(bx + ty + i) * K + by + tx;
        outh[o] = hh;
        outl[o] = ll;
    }
}

// Wfused = W2e @ W1g_bot, written transposed+split into Wcat columns 256..511
__global__ void fuse_w_kernel(const float* __restrict__ w2e,
                              const float* __restrict__ w1g,
                              __half* __restrict__ outh, __half* __restrict__ outl) {
    int k = blockIdx.x, n = threadIdx.x;
    float acc = 0.f;
    for (int j = 0; j < DH; ++j)
        acc = fmaf(w2e[k * DH + j], w1g[(size_t)(DH + j) * DH + n], acc);
    __half hh = __float2half_rn(acc);
    __half ll = __float2half_rn(acc - __half2float(hh));
    outh[(size_t)n * 512 + 256 + k] = hh;
    outl[(size_t)n * 512 + 256 + k] = ll;
}

// cvec = b2e @ W1g_bot
__global__ void cvec_kernel(const float* __restrict__ b2e, const float* __restrict__ w1g) {
    int n = threadIdx.x;
    float acc = 0.f;
    for (int j = 0; j < DH; ++j)
        acc = fmaf(b2e[j], w1g[(size_t)(DH + j) * DH + n], acc);
    g_cvec[n] = acc;
}

// combine+scatter: per edge e (one warp):
//   h1 = relu(mproj[src] + gproj[dst] + b1e);  aggH1[dst] += h1;  deg[dst] += 1
__global__ void combine_kernel(const int* __restrict__ isrc,
                               const int* __restrict__ idst,
                               const float* __restrict__ bias) {
    int e = blockIdx.x * 8 + (threadIdx.x >> 5);
    if (e >= N_EDGE) return;
    int lane = threadIdx.x & 31;
    int s = isrc[e], d = idst[e];
    const float4* mp = (const float4*)(g_mproj + (size_t)s * DH);
    const float4* gp = (const float4*)(g_gproj + (size_t)d * DH);
    const float4* bp = (const float4*)bias;
    float* ap = g_agg + (size_t)d * DH;
    if (lane == 0) red_add_f32(&g_deg[d], 1.0f);
    #pragma unroll
    for (int i = 0; i < 2; ++i) {
        int c = lane + i * 32;
        float4 a = mp[c], b = gp[c], bb = bp[c];
        float4 v;
        v.x = fmaxf(a.x + b.x + bb.x, 0.f);
        v.y = fmaxf(a.y + b.y + bb.y, 0.f);
        v.z = fmaxf(a.z + b.z + bb.z, 0.f);
        v.w = fmaxf(a.w + b.w + bb.w, 0.f);
        red_add_v4(ap + c * 4, v);
    }
}

// ---------------- main GEMM -------------------------------------------------------
// MODE 0: C = A@W, fp32 -> out (projections)
// MODE 2: A = concat(Ah0,Ah1) K=512; epi = relu(acc + b1g + deg*cvec); split -> H2
// MODE 3: A = Ah0 K=256; epi = acc + bias + resid -> out
static constexpr int BK = 32;
static constexpr uint32_t RSTRIDE = 80;
static constexpr uint32_t MATB = 128 * RSTRIDE;
static constexpr uint32_t BUFB = 4 * MATB;
static constexpr uint32_t TILES = 2048;
static constexpr uint32_t SMEM_SZ = TILES + 2 * BUFB;   // 83968 (x2 CTA = 167936 <= 228KB)

template<int MODE, int K>
__global__ __launch_bounds__(256, 2)
void mma_gemm(const __half* __restrict__ Ah0, const __half* __restrict__ Al0,
              const __half* __restrict__ Ah1, const __half* __restrict__ Al1,
              const __half* __restrict__ Wh, const __half* __restrict__ Wl,
              int ldw,
              const float* __restrict__ bias,
              float*       __restrict__ out,
              const float* __restrict__ resid,   // grid_x (M3)
              int M)
{
    extern __shared__ char smem[];
    constexpr int NCH = K / BK;
    const uint32_t sb = smem_u32(smem);

    const int tid  = threadIdx.x;
    const int wid  = tid >> 5;
    const int lane = tid & 31;
    const int m0 = blockIdx.x * 128;
    const int n0 = blockIdx.y * 128;

    float* s_bias = (float*)(smem);          // 256 floats
    float* s_cvec = (float*)(smem + 1024);   // 256 floats (MODE 2)
    if (MODE != 0) s_bias[tid] = bias[tid];
    if (MODE == 2) s_cvec[tid] = g_cvec[tid & 255];
    __syncthreads();

    auto load_chunk = [&](int buf, int kt) {
        const uint32_t ab = sb + TILES + (uint32_t)buf * BUFB;
        #pragma unroll
        for (int it = 0; it < 2; ++it) {
            int e = it * 256 + tid;
            int row = e >> 2;
            int cq = e & 3;
            int rr = m0 + row; if (rr >= M) rr = M - 1;
            const __half *ph, *pl;
            int kk;
            if (MODE == 2) {
                size_t r = (size_t)rr * DH;
                if (kt < DH) { ph = Ah0 + r; pl = Al0 + r; kk = kt; }
                else         { ph = Ah1 + r; pl = Al1 + r; kk = kt - DH; }
            } else {
                size_t r = (size_t)rr * DH;
                ph = Ah0 + r; pl = Al0 + r; kk = kt;
            }
            uint32_t off = (uint32_t)row * RSTRIDE + (uint32_t)cq * 16;
            CP16(ab + off,        ph + kk + cq * 8);
            CP16(ab + MATB + off, pl + kk + cq * 8);
        }
        #pragma unroll
        for (int it = 0; it < 2; ++it) {
            int e = it * 256 + tid;
            int row = e >> 2;
            int cq = e & 3;
            size_t g = (size_t)(n0 + row) * ldw + kt + cq * 8;
            uint32_t off = (uint32_t)row * RSTRIDE + (uint32_t)cq * 16;
            CP16(ab + 2 * MATB + off, Wh + g);
            CP16(ab + 3 * MATB + off, Wl + g);
        }
        CP_COMMIT();
    };

    const int wm = wid & 3;
    const int wn = wid >> 2;

    float acc[2][8][4];
    #pragma unroll
    for (int i = 0; i < 2; ++i)
        #pragma unroll
        for (int j = 0; j < 8; ++j)
            #pragma unroll
            for (int q = 0; q < 4; ++q)
                acc[i][j][q] = 0.f;

    load_chunk(0, 0);

    for (int c = 0; c < NCH; ++c) {
        int buf = c & 1;
        if (c + 1 < NCH) { load_chunk(buf ^ 1, (c + 1) * BK); CP_WAIT1(); }
        else             { CP_WAIT0(); }
        __syncthreads();

        const uint32_t tb = sb + TILES + (uint32_t)buf * BUFB;
        const uint32_t a_base = tb + (uint32_t)(wm * 32 + (lane & 15)) * RSTRIDE
                                   + (uint32_t)((lane >> 4) * 16);
        const uint32_t b_base = tb + 2 * MATB
                                   + (uint32_t)(wn * 64 + ((lane >> 4) & 1) * 8 + (lane & 7)) * RSTRIDE
                                   + (uint32_t)(((lane >> 3) & 1) * 16);
        #pragma unroll
        for (int s = 0; s < 2; ++s) {
            uint32_t ah[2][4], al[2][4];
            LDSM_X4(ah[0], a_base + s * 32);
            LDSM_X4(ah[1], a_base + 16 * RSTRIDE + s * 32);
            LDSM_X4(al[0], a_base + MATB + s * 32);
            LDSM_X4(al[1], a_base + MATB + 16 * RSTRIDE + s * 32);
            #pragma unroll
            for (int p = 0; p < 4; ++p) {
                uint32_t bh[4], bl[4];
                LDSM_X4(bh, b_base + (uint32_t)(p * 16) * RSTRIDE + s * 32);
                LDSM_X4(bl, b_base + MATB + (uint32_t)(p * 16) * RSTRIDE + s * 32);
                MMA16816(acc[0][2*p],   ah[0], bh[0], bh[1]);
                MMA16816(acc[1][2*p],   ah[1], bh[0], bh[1]);
                MMA16816(acc[0][2*p+1], ah[0], bh[2], bh[3]);
                MMA16816(acc[1][2*p+1], ah[1], bh[2], bh[3]);
                MMA16816(acc[0][2*p],   al[0], bh[0], bh[1]);
                MMA16816(acc[1][2*p],   al[1], bh[0], bh[1]);
                MMA16816(acc[0][2*p+1], al[0], bh[2], bh[3]);
                MMA16816(acc[1][2*p+1], al[1], bh[2], bh[3]);
                MMA16816(acc[0][2*p],   ah[0], bl[0], bl[1]);
                MMA16816(acc[1][2*p],   ah[1], bl[0], bl[1]);
                MMA16816(acc[0][2*p+1], ah[0], bl[2], bl[3]);
                MMA16816(acc[1][2*p+1], ah[1], bl[2], bl[3]);
            }
        }
        __syncthreads();
    }

    // ---- epilogue ----
    #pragma unroll
    for (int mt = 0; mt < 2; ++mt) {
        int r0 = m0 + wm * 32 + mt * 16 + (lane >> 2);
        int r1 = r0 + 8;
        float d0 = 0.f, d1 = 0.f;
        if (MODE == 2) {
            if (r0 < M) d0 = g_deg[r0];
            if (r1 < M) d1 = g_deg[r1];
        }
        #pragma unroll
        for (int nt = 0; nt < 8; ++nt) {
            int col = n0 + (wn * 64 + (nt >> 1) * 16 + (nt & 1) * 8) + (lane & 3) * 2;
            float b0 = (MODE != 0) ? s_bias[col & 255] : 0.f;
            float b1 = (MODE != 0) ? s_bias[(col + 1) & 255] : 0.f;
            float v00 = acc[mt][nt][0] + b0, v01 = acc[mt][nt][1] + b1;
            float v10 = acc[mt][nt][2] + b0, v11 = acc[mt][nt][3] + b1;
            if (MODE == 0) {
                if (r0 < M) *(float2*)&out[(size_t)r0 * DH + col] = make_float2(v00, v01);
                if (r1 < M) *(float2*)&out[(size_t)r1 * DH + col] = make_float2(v10, v11);
            } else if (MODE == 2) {
                float c0 = s_cvec[col & 255], c1 = s_cvec[(col + 1) & 255];
                if (r0 < M) {
                    float a = fmaxf(v00 + d0 * c0, 0.f), b = fmaxf(v01 + d0 * c1, 0.f);
                    __half2 hh = __floats2half2_rn(a, b);
                    __half2 ll = __floats2half2_rn(a - __low2float(hh), b - __high2float(hh));
                    *(__half2*)&g_H2h[(size_t)r0 * DH + col] = hh;
                    *(__half2*)&g_H2l[(size_t)r0 * DH + col] = ll;
                }
                if (r1 < M) {
                    float a = fmaxf(v10 + d1 * c0, 0.f), b = fmaxf(v11 + d1 * c1, 0.f);
                    __half2 hh = __floats2half2_rn(a, b);
                    __half2 ll = __floats2half2_rn(a - __low2float(hh), b - __high2float(hh));
                    *(__half2*)&g_H2h[(size_t)r1 * DH + col] = hh;
                    *(__half2*)&g_H2l[(size_t)r1 * DH + col] = ll;
                }
            } else {
                if (r0 < M) {
                    float2 rv = *(const float2*)&resid[(size_t)r0 * DH + col];
                    *(float2*)&out[(size_t)r0 * DH + col] = make_float2(v00 + rv.x, v01 + rv.y);
                }
                if (r1 < M) {
                    float2 rv = *(const float2*)&resid[(size_t)r1 * DH + col];
                    *(float2*)&out[(size_t)r1 * DH + col] = make_float2(v10 + rv.x, v11 + rv.y);
                }
            }
        }
    }
}

// ---------------- launch -----------------------------------------------------------
extern "C" void kernel_launch(void* const* d_in, const int* in_sizes, int n_in,
                              void* d_out, int out_size) {
    const float* mesh_x   = (const float*)d_in[0];
    const float* grid_x   = (const float*)d_in[1];
    const int*   edge_src = (const int*)  d_in[2];
    const int*   edge_dst = (const int*)  d_in[3];
    const float* w1_e = (const float*)d_in[4];
    const float* b1_e = (const float*)d_in[5];
    const float* w2_e = (const float*)d_in[6];
    const float* b2_e = (const float*)d_in[7];
    const float* w1_g = (const float*)d_in[8];
    const float* b1_g = (const float*)d_in[9];
    const float* w2_g = (const float*)d_in[10];
    const float* b2_g = (const float*)d_in[11];
    float* out = (float*)d_out;

    __half *wh, *wl, *mxh, *mxl, *gxh, *gxl, *aggh, *aggl, *h2h, *h2l;
    float *aggf, *mproj, *gproj;
    cudaGetSymbolAddress((void**)&wh,    g_Wh);
    cudaGetSymbolAddress((void**)&wl,    g_Wl);
    cudaGetSymbolAddress((void**)&mxh,   g_mxh);
    cudaGetSymbolAddress((void**)&mxl,   g_mxl);
    cudaGetSymbolAddress((void**)&gxh,   g_gxh);
    cudaGetSymbolAddress((void**)&gxl,   g_gxl);
    cudaGetSymbolAddress((void**)&aggh,  g_aggh);
    cudaGetSymbolAddress((void**)&aggl,  g_aggl);
    cudaGetSymbolAddress((void**)&h2h,   g_H2h);
    cudaGetSymbolAddress((void**)&h2l,   g_H2l);
    cudaGetSymbolAddress((void**)&aggf,  g_agg);
    cudaGetSymbolAddress((void**)&mproj, g_mproj);
    cudaGetSymbolAddress((void**)&gproj, g_gproj);

    __half* wh_e1  = wh;                    __half* wl_e1  = wl;
    __half* wh_cat = wh + 256 * 512;        __half* wl_cat = wl + 256 * 512;
    __half* wh_g2  = wh + 2 * 256 * 512;    __half* wl_g2  = wl + 2 * 256 * 512;

    static bool attr_set = false;
    if (!attr_set) {
        cudaFuncSetAttribute(mma_gemm<0,256>, cudaFuncAttributeMaxDynamicSharedMemorySize, SMEM_SZ);
        cudaFuncSetAttribute(mma_gemm<2,512>, cudaFuncAttributeMaxDynamicSharedMemorySize, SMEM_SZ);
        cudaFuncSetAttribute(mma_gemm<3,256>, cudaFuncAttributeMaxDynamicSharedMemorySize, SMEM_SZ);
        attr_set = true;
    }

    const int GM = (N_MESH + 127) / 128;   // 79
    const int GG = (N_GRID + 127) / 128;   // 782

    // harness issues ~2 launches first; ncu capture = our launch #4
    // 1: zero agg + deg
    zero_kernel<<<25000, 256>>>();
    // 2
    split_kernel<<<(N_GRID * DH / 4 + 255) / 256, 256>>>(
        (const float4*)grid_x, (uint2*)gxh, (uint2*)gxl, N_GRID * DH / 4);
    // 3
    prep_w_kernel<<<dim3(8, 16), dim3(32, 8)>>>(w1_e, wh_e1, wl_e1, 512);
    // 4: grid_proj = grid_x @ W1e_bot   <-- ncu capture
    mma_gemm<0,256><<<dim3(GG,2), 256, SMEM_SZ>>>(gxh, gxl, nullptr, nullptr,
        wh_e1 + 256, wl_e1 + 256, 512, nullptr, gproj, nullptr, N_GRID);
    // 5
    split_kernel<<<(N_MESH * DH / 4 + 255) / 256, 256>>>(
        (const float4*)mesh_x, (uint2*)mxh, (uint2*)mxl, N_MESH * DH / 4);
    // 6: mesh_proj = mesh_x @ W1e_top
    mma_gemm<0,256><<<dim3(GM,2), 256, SMEM_SZ>>>(mxh, mxl, nullptr, nullptr,
        wh_e1, wl_e1, 512, nullptr, mproj, nullptr, N_MESH);
    // 7: combine + scatter H1 into aggH1, count deg
    combine_kernel<<<N_EDGE / 8, 256>>>(edge_src, edge_dst, b1_e);
    // 8: split aggH1
    split_kernel<<<(N_GRID * DH / 4 + 255) / 256, 256>>>(
        (const float4*)aggf, (uint2*)aggh, (uint2*)aggl, N_GRID * DH / 4);
    // 9: W1g_top transposed into Wcat cols 0..255
    prep_w_kernel<<<dim3(8, 8), dim3(32, 8)>>>(w1_g, wh_cat, wl_cat, 512);
    // 10: Wfused = W2e @ W1g_bot into Wcat cols 256..511
    fuse_w_kernel<<<256, 256>>>(w2_e, w1_g, wh_cat, wl_cat);
    // 11: cvec = b2e @ W1g_bot
    cvec_kernel<<<1, 256>>>(b2_e, w1_g);
    // 12: grid L1 (fused): relu(gx@W1g_top + aggH1@Wfused + deg*cvec + b1g) -> H2
    mma_gemm<2,512><<<dim3(GG,2), 256, SMEM_SZ>>>(gxh, gxl, aggh, aggl,
        wh_cat, wl_cat, 512, b1_g, nullptr, nullptr, N_GRID);
    // 13
    prep_w_kernel<<<dim3(8, 8), dim3(32, 8)>>>(w2_g, wh_g2, wl_g2, 256);
    // 14: grid L2 + residual
    mma_gemm<3,256><<<dim3(GG,2), 256, SMEM_SZ>>>(h2h, h2l, nullptr, nullptr,
        wh_g2, wl_g2, 256, b2_g, out, grid_x, N_GRID);
}

// round 8
// speedup vs baseline: 5.8707x; 1.0637x over previous
#include <cuda_runtime.h>
#include <cuda_fp16.h>
#include <cstdint>

#define N_MESH 10000
#define N_GRID 100000
#define N_EDGE 300000
#define DH     256

// ---------------- device scratch ----------------------------------------------
__device__ float g_agg[(size_t)N_GRID * DH];     // aggH1 = segment_sum(H1)
__device__ float g_deg[N_GRID];                  // edge count per grid node
__device__ float g_cvec[DH];                     // b2e @ W1g_bot
__device__ float g_mproj[(size_t)N_MESH * DH];   // mesh_x @ W1e_top
__device__ float g_gproj[(size_t)N_GRID * DH];   // grid_x @ W1e_bot
__device__ __align__(16) __half g_mxh[(size_t)N_MESH * DH];
__device__ __align__(16) __half g_mxl[(size_t)N_MESH * DH];
__device__ __align__(16) __half g_gxh[(size_t)N_GRID * DH];
__device__ __align__(16) __half g_gxl[(size_t)N_GRID * DH];
__device__ __align__(16) __half g_aggh[(size_t)N_GRID * DH];
__device__ __align__(16) __half g_aggl[(size_t)N_GRID * DH];
__device__ __align__(16) __half g_H2h[(size_t)N_GRID * DH];
__device__ __align__(16) __half g_H2l[(size_t)N_GRID * DH];
// weight arena: [0) W1e_T (256x512) | [256*512) Wcat (256x512) | [2*256*512) W2g_T (256x256)
__device__ __align__(16) __half g_Wh[2 * 256 * 512 + 256 * 256];
__device__ __align__(16) __half g_Wl[2 * 256 * 512 + 256 * 256];

// ---------------- helpers -------------------------------------------------------
__device__ __forceinline__ uint32_t smem_u32(const void* p) {
    uint32_t a;
    asm("{ .reg .u64 t; cvta.to.shared.u64 t, %1; cvt.u32.u64 %0, t; }"
        : "=r"(a) : "l"(p));
    return a;
}

#define LDSM_X4(r, addr)                                                     \
    asm volatile("ldmatrix.sync.aligned.m8n8.x4.shared.b16 {%0,%1,%2,%3}, [%4];" \
        : "=r"((r)[0]), "=r"((r)[1]), "=r"((r)[2]), "=r"((r)[3]) : "r"(addr))

#define MMA16816(c, a, b0, b1)                                               \
    asm volatile("mma.sync.aligned.m16n8k16.row.col.f32.f16.f16.f32 "        \
        "{%0,%1,%2,%3}, {%4,%5,%6,%7}, {%8,%9}, {%0,%1,%2,%3};"              \
        : "+f"((c)[0]), "+f"((c)[1]), "+f"((c)[2]), "+f"((c)[3])             \
        : "r"((a)[0]), "r"((a)[1]), "r"((a)[2]), "r"((a)[3]), "r"(b0), "r"(b1))

#define CP16(dst, src) \
    asm volatile("cp.async.cg.shared.global [%0], [%1], 16;" :: "r"(dst), "l"(src))
#define CP_COMMIT() asm volatile("cp.async.commit_group;")
#define CP_WAIT1()  asm volatile("cp.async.wait_group 1;")
#define CP_WAIT0()  asm volatile("cp.async.wait_group 0;")

__device__ __forceinline__ void red_add_v4(float* p, float4 v) {
    asm volatile("red.global.add.v4.f32 [%0], {%1,%2,%3,%4};"
                 :: "l"(p), "f"(v.x), "f"(v.y), "f"(v.z), "f"(v.w) : "memory");
}
__device__ __forceinline__ void red_add_f32(float* p, float v) {
    asm volatile("red.global.add.f32 [%0], %1;" :: "l"(p), "f"(v) : "memory");
}

// ---------------- aux kernels ----------------------------------------------------
__global__ void zero_kernel() {
    size_t i = ((size_t)blockIdx.x * blockDim.x + threadIdx.x) * 4;
    if (i < (size_t)N_GRID * DH)
        *(float4*)&g_agg[i] = make_float4(0.f, 0.f, 0.f, 0.f);
    if (i < N_GRID)
        *(float4*)&g_deg[i] = make_float4(0.f, 0.f, 0.f, 0.f);
}

__global__ void split_kernel(const float4* __restrict__ in,
                             uint2* __restrict__ h, uint2* __restrict__ l, int n4) {
    int i = blockIdx.x * blockDim.x + threadIdx.x;
    if (i >= n4) return;
    float4 v = in[i];
    __half2 h01 = __floats2half2_rn(v.x, v.y);
    __half2 h23 = __floats2half2_rn(v.z, v.w);
    __half2 l01 = __floats2half2_rn(v.x - __low2float(h01), v.y - __high2float(h01));
    __half2 l23 = __floats2half2_rn(v.z - __low2float(h23), v.w - __high2float(h23));
    h[i] = make_uint2(*(uint32_t*)&h01, *(uint32_t*)&h23);
    l[i] = make_uint2(*(uint32_t*)&l01, *(uint32_t*)&l23);
}

// weights: in[k][256] fp32 -> outh/outl[n][K] fp16 (transpose + split)
__global__ void prep_w_kernel(const float* __restrict__ in,
                              __half* __restrict__ outh,
                              __half* __restrict__ outl, int K) {
    __shared__ float t[32][33];
    int bx = blockIdx.x * 32, by = blockIdx.y * 32;
    int tx = threadIdx.x, ty = threadIdx.y;
    #pragma unroll
    for (int i = 0; i < 32; i += 8)
        t[ty + i][tx] = in[(size_t)(by + ty + i) * DH + bx + tx];
    __syncthreads();
    #pragma unroll
    for (int i = 0; i < 32; i += 8) {
        float v = t[tx][ty + i];
        __half hh = __float2half_rn(v);
        __half ll = __float2half_rn(v - __half2float(hh));
        size_t o = (size_t)(bx + ty + i) * K + by + tx;
        outh[o] = hh;
        outl[o] = ll;
    }
}

// Wfused = W2e @ W1g_bot, written transposed+split into Wcat columns 256..511
__global__ void fuse_w_kernel(const float* __restrict__ w2e,
                              const float* __restrict__ w1g,
                              __half* __restrict__ outh, __half* __restrict__ outl) {
    int k = blockIdx.x, n = threadIdx.x;
    float acc = 0.f;
    for (int j = 0; j < DH; ++j)
        acc = fmaf(w2e[k * DH + j], w1g[(size_t)(DH + j) * DH + n], acc);
    __half hh = __float2half_rn(acc);
    __half ll = __float2half_rn(acc - __half2float(hh));
    outh[(size_t)n * 512 + 256 + k] = hh;
    outl[(size_t)n * 512 + 256 + k] = ll;
}

// cvec = b2e @ W1g_bot
__global__ void cvec_kernel(const float* __restrict__ b2e, const float* __restrict__ w1g) {
    int n = threadIdx.x;
    float acc = 0.f;
    for (int j = 0; j < DH; ++j)
        acc = fmaf(b2e[j], w1g[(size_t)(DH + j) * DH + n], acc);
    g_cvec[n] = acc;
}

// combine+scatter: per edge e (one warp):
//   h1 = relu(mproj[src] + gproj[dst] + b1e);  aggH1[dst] += h1;  deg[dst] += 1
__global__ void combine_kernel(const int* __restrict__ isrc,
                               const int* __restrict__ idst,
                               const float* __restrict__ bias) {
    int e = blockIdx.x * 8 + (threadIdx.x >> 5);
    if (e >= N_EDGE) return;
    int lane = threadIdx.x & 31;
    int s = isrc[e], d = idst[e];
    const float4* mp = (const float4*)(g_mproj + (size_t)s * DH);
    const float4* gp = (const float4*)(g_gproj + (size_t)d * DH);
    const float4* bp = (const float4*)bias;
    float* ap = g_agg + (size_t)d * DH;
    if (lane == 0) red_add_f32(&g_deg[d], 1.0f);
    #pragma unroll
    for (int i = 0; i < 2; ++i) {
        int c = lane + i * 32;
        float4 a = mp[c], b = gp[c], bb = bp[c];
        float4 v;
        v.x = fmaxf(a.x + b.x + bb.x, 0.f);
        v.y = fmaxf(a.y + b.y + bb.y, 0.f);
        v.z = fmaxf(a.z + b.z + bb.z, 0.f);
        v.w = fmaxf(a.w + b.w + bb.w, 0.f);
        red_add_v4(ap + c * 4, v);
    }
}

// ---------------- main GEMM -------------------------------------------------------
// 128x128 tile, BK=32, 8 warps, 2 CTAs/SM, 3-stage cp.async pipeline,
// XOR-swizzled 64B smem rows (no padding).
// MODE 0: C = A@W, fp32 -> out (projections)
// MODE 2: A = concat(Ah0,Ah1) K=512; epi = relu(acc + b1g + deg*cvec); split -> H2
// MODE 3: A = Ah0 K=256; epi = acc + bias + resid -> out
static constexpr int BK = 32;
static constexpr uint32_t MATB = 128 * 64;        // 8192 B per matrix (no padding)
static constexpr uint32_t BUFB = 4 * MATB;        // Ah, Al, Bh, Bl = 32768
static constexpr uint32_t NSTAGE = 3;
static constexpr uint32_t TILES = 2048;
static constexpr uint32_t SMEM_SZ = TILES + NSTAGE * BUFB;  // 100352 (x2 = 200704)

// swizzle: 16B quad q at row r stored at quad (q ^ ((r>>1)&3))
__device__ __forceinline__ uint32_t swz(uint32_t row, uint32_t q) {
    return row * 64u + ((q ^ ((row >> 1) & 3u)) << 4);
}

template<int MODE, int K>
__global__ __launch_bounds__(256, 2)
void mma_gemm(const __half* __restrict__ Ah0, const __half* __restrict__ Al0,
              const __half* __restrict__ Ah1, const __half* __restrict__ Al1,
              const __half* __restrict__ Wh, const __half* __restrict__ Wl,
              int ldw,
              const float* __restrict__ bias,
              float*       __restrict__ out,
              const float* __restrict__ resid,   // grid_x (M3)
              int M)
{
    extern __shared__ char smem[];
    constexpr int NCH = K / BK;
    const uint32_t sb = smem_u32(smem);

    const int tid  = threadIdx.x;
    const int wid  = tid >> 5;
    const int lane = tid & 31;
    const int m0 = blockIdx.x * 128;
    const int n0 = blockIdx.y * 128;

    float* s_bias = (float*)(smem);          // 256 floats
    float* s_cvec = (float*)(smem + 1024);   // 256 floats (MODE 2)
    if (MODE != 0) s_bias[tid] = bias[tid];
    if (MODE == 2) s_cvec[tid] = g_cvec[tid & 255];
    __syncthreads();

    auto load_chunk = [&](int buf, int kt) {
        const uint32_t ab = sb + TILES + (uint32_t)buf * BUFB;
        #pragma unroll
        for (int it = 0; it < 2; ++it) {
            int e = it * 256 + tid;
            uint32_t row = (uint32_t)e >> 2;
            uint32_t cq = (uint32_t)e & 3;
            int rr = m0 + (int)row; if (rr >= M) rr = M - 1;
            const __half *ph, *pl;
            int kk;
            if (MODE == 2) {
                size_t r = (size_t)rr * DH;
                if (kt < DH) { ph = Ah0 + r; pl = Al0 + r; kk = kt; }
                else         { ph = Ah1 + r; pl = Al1 + r; kk = kt - DH; }
            } else {
                size_t r = (size_t)rr * DH;
                ph = Ah0 + r; pl = Al0 + r; kk = kt;
            }
            uint32_t off = swz(row, cq);
            CP16(ab + off,        ph + kk + cq * 8);
            CP16(ab + MATB + off, pl + kk + cq * 8);
        }
        #pragma unroll
        for (int it = 0; it < 2; ++it) {
            int e = it * 256 + tid;
            uint32_t row = (uint32_t)e >> 2;
            uint32_t cq = (uint32_t)e & 3;
            size_t g = (size_t)(n0 + (int)row) * ldw + kt + cq * 8;
            uint32_t off = swz(row, cq);
            CP16(ab + 2 * MATB + off, Wh + g);
            CP16(ab + 3 * MATB + off, Wl + g);
        }
        CP_COMMIT();
    };

    const int wm = wid & 3;
    const int wn = wid >> 2;

    // per-lane swizzled base offsets (invariant under +16-row steps)
    const uint32_t rowA = (uint32_t)(wm * 32 + (lane & 15));
    const uint32_t aoff = swz(rowA, (uint32_t)(lane >> 4));
    const uint32_t rowB = (uint32_t)(wn * 64 + ((lane >> 4) & 1) * 8 + (lane & 7));
    const uint32_t boff = swz(rowB, (uint32_t)((lane >> 3) & 1));

    float acc[2][8][4];
    #pragma unroll
    for (int i = 0; i < 2; ++i)
        #pragma unroll
        for (int j = 0; j < 8; ++j)
            #pragma unroll
            for (int q = 0; q < 4; ++q)
                acc[i][j][q] = 0.f;

    load_chunk(0, 0);
    if (NCH > 1) load_chunk(1, BK);

    for (int c = 0; c < NCH; ++c) {
        int buf = c % NSTAGE;
        if (c + 1 < NCH) CP_WAIT1(); else CP_WAIT0();
        __syncthreads();
        if (c + 2 < NCH) load_chunk((c + 2) % NSTAGE, (c + 2) * BK);

        const uint32_t tb = sb + TILES + (uint32_t)buf * BUFB;
        #pragma unroll
        for (int s = 0; s < 2; ++s) {
            const uint32_t sx = (uint32_t)s << 5;
            uint32_t ah[2][4], al[2][4];
            LDSM_X4(ah[0], tb + (aoff ^ sx));
            LDSM_X4(ah[1], tb + ((aoff + 1024u) ^ sx));
            LDSM_X4(al[0], tb + MATB + (aoff ^ sx));
            LDSM_X4(al[1], tb + MATB + ((aoff + 1024u) ^ sx));
            #pragma unroll
            for (int p = 0; p < 4; ++p) {
                uint32_t bh[4], bl[4];
                LDSM_X4(bh, tb + 2 * MATB + ((boff + (uint32_t)p * 1024u) ^ sx));
                LDSM_X4(bl, tb + 3 * MATB + ((boff + (uint32_t)p * 1024u) ^ sx));
                MMA16816(acc[0][2*p],   ah[0], bh[0], bh[1]);
                MMA16816(acc[1][2*p],   ah[1], bh[0], bh[1]);
                MMA16816(acc[0][2*p+1], ah[0], bh[2], bh[3]);
                MMA16816(acc[1][2*p+1], ah[1], bh[2], bh[3]);
                MMA16816(acc[0][2*p],   al[0], bh[0], bh[1]);
                MMA16816(acc[1][2*p],   al[1], bh[0], bh[1]);
                MMA16816(acc[0][2*p+1], al[0], bh[2], bh[3]);
                MMA16816(acc[1][2*p+1], al[1], bh[2], bh[3]);
                MMA16816(acc[0][2*p],   ah[0], bl[0], bl[1]);
                MMA16816(acc[1][2*p],   ah[1], bl[0], bl[1]);
                MMA16816(acc[0][2*p+1], ah[0], bl[2], bl[3]);
                MMA16816(acc[1][2*p+1], ah[1], bl[2], bl[3]);
            }
        }
    }
    __syncthreads();

    // ---- epilogue ----
    #pragma unroll
    for (int mt = 0; mt < 2; ++mt) {
        int r0 = m0 + wm * 32 + mt * 16 + (lane >> 2);
        int r1 = r0 + 8;
        float d0 = 0.f, d1 = 0.f;
        if (MODE == 2) {
            if (r0 < M) d0 = g_deg[r0];
            if (r1 < M) d1 = g_deg[r1];
        }
        #pragma unroll
        for (int nt = 0; nt < 8; ++nt) {
            int col = n0 + (wn * 64 + (nt >> 1) * 16 + (nt & 1) * 8) + (lane & 3) * 2;
            float b0 = (MODE != 0) ? s_bias[col & 255] : 0.f;
            float b1 = (MODE != 0) ? s_bias[(col + 1) & 255] : 0.f;
            float v00 = acc[mt][nt][0] + b0, v01 = acc[mt][nt][1] + b1;
            float v10 = acc[mt][nt][2] + b0, v11 = acc[mt][nt][3] + b1;
            if (MODE == 0) {
                if (r0 < M) *(float2*)&out[(size_t)r0 * DH + col] = make_float2(v00, v01);
                if (r1 < M) *(float2*)&out[(size_t)r1 * DH + col] = make_float2(v10, v11);
            } else if (MODE == 2) {
                float c0 = s_cvec[col & 255], c1 = s_cvec[(col + 1) & 255];
                if (r0 < M) {
                    float a = fmaxf(v00 + d0 * c0, 0.f), b = fmaxf(v01 + d0 * c1, 0.f);
                    __half2 hh = __floats2half2_rn(a, b);
                    __half2 ll = __floats2half2_rn(a - __low2float(hh), b - __high2float(hh));
                    *(__half2*)&g_H2h[(size_t)r0 * DH + col] = hh;
                    *(__half2*)&g_H2l[(size_t)r0 * DH + col] = ll;
                }
                if (r1 < M) {
                    float a = fmaxf(v10 + d1 * c0, 0.f), b = fmaxf(v11 + d1 * c1, 0.f);
                    __half2 hh = __floats2half2_rn(a, b);
                    __half2 ll = __floats2half2_rn(a - __low2float(hh), b - __high2float(hh));
                    *(__half2*)&g_H2h[(size_t)r1 * DH + col] = hh;
                    *(__half2*)&g_H2l[(size_t)r1 * DH + col] = ll;
                }
            } else {
                if (r0 < M) {
                    float2 rv = *(const float2*)&resid[(size_t)r0 * DH + col];
                    *(float2*)&out[(size_t)r0 * DH + col] = make_float2(v00 + rv.x, v01 + rv.y);
                }
                if (r1 < M) {
                    float2 rv = *(const float2*)&resid[(size_t)r1 * DH + col];
                    *(float2*)&out[(size_t)r1 * DH + col] = make_float2(v10 + rv.x, v11 + rv.y);
                }
            }
        }
    }
}

// ---------------- launch -----------------------------------------------------------
extern "C" void kernel_launch(void* const* d_in, const int* in_sizes, int n_in,
                              void* d_out, int out_size) {
    const float* mesh_x   = (const float*)d_in[0];
    const float* grid_x   = (const float*)d_in[1];
    const int*   edge_src = (const int*)  d_in[2];
    const int*   edge_dst = (const int*)  d_in[3];
    const float* w1_e = (const float*)d_in[4];
    const float* b1_e = (const float*)d_in[5];
    const float* w2_e = (const float*)d_in[6];
    const float* b2_e = (const float*)d_in[7];
    const float* w1_g = (const float*)d_in[8];
    const float* b1_g = (const float*)d_in[9];
    const float* w2_g = (const float*)d_in[10];
    const float* b2_g = (const float*)d_in[11];
    float* out = (float*)d_out;

    __half *wh, *wl, *mxh, *mxl, *gxh, *gxl, *aggh, *aggl, *h2h, *h2l;
    float *aggf, *mproj, *gproj;
    cudaGetSymbolAddress((void**)&wh,    g_Wh);
    cudaGetSymbolAddress((void**)&wl,    g_Wl);
    cudaGetSymbolAddress((void**)&mxh,   g_mxh);
    cudaGetSymbolAddress((void**)&mxl,   g_mxl);
    cudaGetSymbolAddress((void**)&gxh,   g_gxh);
    cudaGetSymbolAddress((void**)&gxl,   g_gxl);
    cudaGetSymbolAddress((void**)&aggh,  g_aggh);
    cudaGetSymbolAddress((void**)&aggl,  g_aggl);
    cudaGetSymbolAddress((void**)&h2h,   g_H2h);
    cudaGetSymbolAddress((void**)&h2l,   g_H2l);
    cudaGetSymbolAddress((void**)&aggf,  g_agg);
    cudaGetSymbolAddress((void**)&mproj, g_mproj);
    cudaGetSymbolAddress((void**)&gproj, g_gproj);

    __half* wh_e1  = wh;                    __half* wl_e1  = wl;
    __half* wh_cat = wh + 256 * 512;        __half* wl_cat = wl + 256 * 512;
    __half* wh_g2  = wh + 2 * 256 * 512;    __half* wl_g2  = wl + 2 * 256 * 512;

    static bool attr_set = false;
    if (!attr_set) {
        cudaFuncSetAttribute(mma_gemm<0,256>, cudaFuncAttributeMaxDynamicSharedMemorySize, SMEM_SZ);
        cudaFuncSetAttribute(mma_gemm<2,512>, cudaFuncAttributeMaxDynamicSharedMemorySize, SMEM_SZ);
        cudaFuncSetAttribute(mma_gemm<3,256>, cudaFuncAttributeMaxDynamicSharedMemorySize, SMEM_SZ);
        attr_set = true;
    }

    const int GM = (N_MESH + 127) / 128;   // 79
    const int GG = (N_GRID + 127) / 128;   // 782

    // harness issues ~2 launches first; ncu capture = our launch #4
    // 1: zero agg + deg
    zero_kernel<<<25000, 256>>>();
    // 2
    split_kernel<<<(N_GRID * DH / 4 + 255) / 256, 256>>>(
        (const float4*)grid_x, (uint2*)gxh, (uint2*)gxl, N_GRID * DH / 4);
    // 3
    prep_w_kernel<<<dim3(8, 16), dim3(32, 8)>>>(w1_e, wh_e1, wl_e1, 512);
    // 4: grid_proj = grid_x @ W1e_bot   <-- ncu capture
    mma_gemm<0,256><<<dim3(GG,2), 256, SMEM_SZ>>>(gxh, gxl, nullptr, nullptr,
        wh_e1 + 256, wl_e1 + 256, 512, nullptr, gproj, nullptr, N_GRID);
    // 5
    split_kernel<<<(N_MESH * DH / 4 + 255) / 256, 256>>>(
        (const float4*)mesh_x, (uint2*)mxh, (uint2*)mxl, N_MESH * DH / 4);
    // 6: mesh_proj = mesh_x @ W1e_top
    mma_gemm<0,256><<<dim3(GM,2), 256, SMEM_SZ>>>(mxh, mxl, nullptr, nullptr,
        wh_e1, wl_e1, 512, nullptr, mproj, nullptr, N_MESH);
    // 7: combine + scatter H1 into aggH1, count deg
    combine_kernel<<<N_EDGE / 8, 256>>>(edge_src, edge_dst, b1_e);
    // 8: split aggH1
    split_kernel<<<(N_GRID * DH / 4 + 255) / 256, 256>>>(
        (const float4*)aggf, (uint2*)aggh, (uint2*)aggl, N_GRID * DH / 4);
    // 9: W1g_top transposed into Wcat cols 0..255
    prep_w_kernel<<<dim3(8, 8), dim3(32, 8)>>>(w1_g, wh_cat, wl_cat, 512);
    // 10: Wfused = W2e @ W1g_bot into Wcat cols 256..511
    fuse_w_kernel<<<256, 256>>>(w2_e, w1_g, wh_cat, wl_cat);
    // 11: cvec = b2e @ W1g_bot
    cvec_kernel<<<1, 256>>>(b2_e, w1_g);
    // 12: grid L1 (fused): relu(gx@W1g_top + aggH1@Wfused + deg*cvec + b1g) -> H2
    mma_gemm<2,512><<<dim3(GG,2), 256, SMEM_SZ>>>(gxh, gxl, aggh, aggl,
        wh_cat, wl_cat, 512, b1_g, nullptr, nullptr, N_GRID);
    // 13
    prep_w_kernel<<<dim3(8, 8), dim3(32, 8)>>>(w2_g, wh_g2, wl_g2, 256);
    // 14: grid L2 + residual
    mma_gemm<3,256><<<dim3(GG,2), 256, SMEM_SZ>>>(h2h, h2l, nullptr, nullptr,
        wh_g2, wl_g2, 256, b2_g, out, grid_x, N_GRID);
}

// round 9
// speedup vs baseline: 6.1876x; 1.0540x over previous
#include <cuda_runtime.h>
#include <cuda_fp16.h>
#include <cstdint>

#define N_MESH 10000
#define N_GRID 100000
#define N_EDGE 300000
#define DH     256

// ---------------- device scratch ----------------------------------------------
__device__ float g_agg[(size_t)N_GRID * DH];     // aggH1 = segment_sum(H1)
__device__ float g_deg[N_GRID];                  // edge count per grid node
__device__ float g_cvec[DH];                     // b2e @ W1g_bot
__device__ float g_mproj[(size_t)N_MESH * DH];   // mesh_x @ W1e_top
__device__ float g_gproj[(size_t)N_GRID * DH];   // grid_x @ W1e_bot
__device__ __align__(16) __half g_mxh[(size_t)N_MESH * DH];
__device__ __align__(16) __half g_mxl[(size_t)N_MESH * DH];
__device__ __align__(16) __half g_gxh[(size_t)N_GRID * DH];
__device__ __align__(16) __half g_gxl[(size_t)N_GRID * DH];
__device__ __align__(16) __half g_aggh[(size_t)N_GRID * DH];
__device__ __align__(16) __half g_aggl[(size_t)N_GRID * DH];
__device__ __align__(16) __half g_H2h[(size_t)N_GRID * DH];
__device__ __align__(16) __half g_H2l[(size_t)N_GRID * DH];
// weight arena: [0) W1e_T (256x512) | [256*512) Wcat (256x512) | [2*256*512) W2g_T (256x256)
__device__ __align__(16) __half g_Wh[2 * 256 * 512 + 256 * 256];
__device__ __align__(16) __half g_Wl[2 * 256 * 512 + 256 * 256];

// ---------------- helpers -------------------------------------------------------
__device__ __forceinline__ uint32_t smem_u32(const void* p) {
    uint32_t a;
    asm("{ .reg .u64 t; cvta.to.shared.u64 t, %1; cvt.u32.u64 %0, t; }"
        : "=r"(a) : "l"(p));
    return a;
}

#define LDSM_X4(r, addr)                                                     \
    asm volatile("ldmatrix.sync.aligned.m8n8.x4.shared.b16 {%0,%1,%2,%3}, [%4];" \
        : "=r"((r)[0]), "=r"((r)[1]), "=r"((r)[2]), "=r"((r)[3]) : "r"(addr))

#define MMA16816(c, a, b0, b1)                                               \
    asm volatile("mma.sync.aligned.m16n8k16.row.col.f32.f16.f16.f32 "        \
        "{%0,%1,%2,%3}, {%4,%5,%6,%7}, {%8,%9}, {%0,%1,%2,%3};"              \
        : "+f"((c)[0]), "+f"((c)[1]), "+f"((c)[2]), "+f"((c)[3])             \
        : "r"((a)[0]), "r"((a)[1]), "r"((a)[2]), "r"((a)[3]), "r"(b0), "r"(b1))

#define CP16(dst, src) \
    asm volatile("cp.async.cg.shared.global [%0], [%1], 16;" :: "r"(dst), "l"(src))
#define CP_COMMIT() asm volatile("cp.async.commit_group;")
#define CP_WAIT1()  asm volatile("cp.async.wait_group 1;")
#define CP_WAIT0()  asm volatile("cp.async.wait_group 0;")

__device__ __forceinline__ void red_add_v4(float* p, float4 v) {
    asm volatile("red.global.add.v4.f32 [%0], {%1,%2,%3,%4};"
                 :: "l"(p), "f"(v.x), "f"(v.y), "f"(v.z), "f"(v.w) : "memory");
}
__device__ __forceinline__ void red_add_f32(float* p, float v) {
    asm volatile("red.global.add.f32 [%0], %1;" :: "l"(p), "f"(v) : "memory");
}

// ---------------- aux kernels ----------------------------------------------------
__global__ void zero_kernel() {
    size_t i = ((size_t)blockIdx.x * blockDim.x + threadIdx.x) * 4;
    if (i < (size_t)N_GRID * DH)
        *(float4*)&g_agg[i] = make_float4(0.f, 0.f, 0.f, 0.f);
    if (i < N_GRID)
        *(float4*)&g_deg[i] = make_float4(0.f, 0.f, 0.f, 0.f);
}

// split grid_x AND mesh_x in one launch
__global__ void split2_kernel(const float4* __restrict__ gx, const float4* __restrict__ mx) {
    int i = blockIdx.x * blockDim.x + threadIdx.x;
    const int NG4 = N_GRID * DH / 4;
    const int NM4 = N_MESH * DH / 4;
    float4 v;
    uint2 *hp, *lp;
    if (i < NG4) {
        v = gx[i];
        hp = (uint2*)g_gxh + i; lp = (uint2*)g_gxl + i;
    } else if (i < NG4 + NM4) {
        int j = i - NG4;
        v = mx[j];
        hp = (uint2*)g_mxh + j; lp = (uint2*)g_mxl + j;
    } else return;
    __half2 h01 = __floats2half2_rn(v.x, v.y);
    __half2 h23 = __floats2half2_rn(v.z, v.w);
    __half2 l01 = __floats2half2_rn(v.x - __low2float(h01), v.y - __high2float(h01));
    __half2 l23 = __floats2half2_rn(v.z - __low2float(h23), v.w - __high2float(h23));
    *hp = make_uint2(*(uint32_t*)&h01, *(uint32_t*)&h23);
    *lp = make_uint2(*(uint32_t*)&l01, *(uint32_t*)&l23);
}

__global__ void split_kernel(const float4* __restrict__ in,
                             uint2* __restrict__ h, uint2* __restrict__ l, int n4) {
    int i = blockIdx.x * blockDim.x + threadIdx.x;
    if (i >= n4) return;
    float4 v = in[i];
    __half2 h01 = __floats2half2_rn(v.x, v.y);
    __half2 h23 = __floats2half2_rn(v.z, v.w);
    __half2 l01 = __floats2half2_rn(v.x - __low2float(h01), v.y - __high2float(h01));
    __half2 l23 = __floats2half2_rn(v.z - __low2float(h23), v.w - __high2float(h23));
    h[i] = make_uint2(*(uint32_t*)&h01, *(uint32_t*)&h23);
    l[i] = make_uint2(*(uint32_t*)&l01, *(uint32_t*)&l23);
}

// weights: in[k][256] fp32 -> outh/outl[n][K] fp16 (transpose + split)
__global__ void prep_w_kernel(const float* __restrict__ in,
                              __half* __restrict__ outh,
                              __half* __restrict__ outl, int K) {
    __shared__ float t[32][33];
    int bx = blockIdx.x * 32, by = blockIdx.y * 32;
    int tx = threadIdx.x, ty = threadIdx.y;
    #pragma unroll
    for (int i = 0; i < 32; i += 8)
        t[ty + i][tx] = in[(size_t)(by + ty + i) * DH + bx + tx];
    __syncthreads();
    #pragma unroll
    for (int i = 0; i < 32; i += 8) {
        float v = t[tx][ty + i];
        __half hh = __float2half_rn(v);
        __half ll = __float2half_rn(v - __half2float(hh));
        size_t o = (size_t)(bx + ty + i) * K + by + tx;
        outh[o] = hh;
        outl[o] = ll;
    }
}

// blocks 0..255: Wfused = W2e @ W1g_bot into Wcat cols 256..511; block 256: cvec
__global__ void fuse_w_kernel(const float* __restrict__ w2e,
                              const float* __restrict__ w1g,
                              const float* __restrict__ b2e,
                              __half* __restrict__ outh, __half* __restrict__ outl) {
    int n = threadIdx.x;
    if (blockIdx.x == 256) {
        float acc = 0.f;
        for (int j = 0; j < DH; ++j)
            acc = fmaf(b2e[j], w1g[(size_t)(DH + j) * DH + n], acc);
        g_cvec[n] = acc;
        return;
    }
    int k = blockIdx.x;
    float acc = 0.f;
    for (int j = 0; j < DH; ++j)
        acc = fmaf(w2e[k * DH + j], w1g[(size_t)(DH + j) * DH + n], acc);
    __half hh = __float2half_rn(acc);
    __half ll = __float2half_rn(acc - __half2float(hh));
    outh[(size_t)n * 512 + 256 + k] = hh;
    outl[(size_t)n * 512 + 256 + k] = ll;
}

// combine+scatter: per edge e (one warp):
//   h1 = relu(mproj[src] + gproj[dst] + b1e);  aggH1[dst] += h1;  deg[dst] += 1
__global__ void combine_kernel(const int* __restrict__ isrc,
                               const int* __restrict__ idst,
                               const float* __restrict__ bias) {
    int e = blockIdx.x * 8 + (threadIdx.x >> 5);
    if (e >= N_EDGE) return;
    int lane = threadIdx.x & 31;
    int s = isrc[e], d = idst[e];
    const float4* mp = (const float4*)(g_mproj + (size_t)s * DH);
    const float4* gp = (const float4*)(g_gproj + (size_t)d * DH);
    const float4* bp = (const float4*)bias;
    float* ap = g_agg + (size_t)d * DH;
    if (lane == 0) red_add_f32(&g_deg[d], 1.0f);
    #pragma unroll
    for (int i = 0; i < 2; ++i) {
        int c = lane + i * 32;
        float4 a = mp[c], b = gp[c], bb = bp[c];
        float4 v;
        v.x = fmaxf(a.x + b.x + bb.x, 0.f);
        v.y = fmaxf(a.y + b.y + bb.y, 0.f);
        v.z = fmaxf(a.z + b.z + bb.z, 0.f);
        v.w = fmaxf(a.w + b.w + bb.w, 0.f);
        red_add_v4(ap + c * 4, v);
    }
}

// ---------------- main GEMM -------------------------------------------------------
// 128x128 tile, BK=32, 8 warps, 2 CTAs/SM, 3-stage cp.async pipeline,
// XOR-swizzled 64B rows, K-chunk order staggered across co-resident CTAs.
// MODE 0: C = A@W fp32 (projections; blocks >= nblk_g handle the mesh GEMM)
// MODE 2: A = concat(Ah0,Ah1) K=512; epi = relu(acc + b1g + deg*cvec); split -> H2
// MODE 3: A = Ah0 K=256; epi = acc + bias + resid -> out
static constexpr int BK = 32;
static constexpr uint32_t MATB = 128 * 64;        // 8192 B per matrix
static constexpr uint32_t BUFB = 4 * MATB;        // 32768
static constexpr uint32_t NSTAGE = 3;
static constexpr uint32_t TILES = 2048;
static constexpr uint32_t SMEM_SZ = TILES + NSTAGE * BUFB;  // 100352 (x2 = 200704)

__device__ __forceinline__ uint32_t swz(uint32_t row, uint32_t q) {
    return row * 64u + ((q ^ ((row >> 1) & 3u)) << 4);
}

template<int MODE, int K>
__global__ __launch_bounds__(256, 2)
void mma_gemm(const __half* __restrict__ pAh0, const __half* __restrict__ pAl0,
              const __half* __restrict__ Ah1, const __half* __restrict__ Al1,
              const __half* __restrict__ pWh, const __half* __restrict__ pWl,
              int ldw,
              const float* __restrict__ bias,
              float*       __restrict__ pout,
              const float* __restrict__ resid,
              int pM,
              // mesh-merge set (MODE 0 only)
              const __half* __restrict__ Ah0m, const __half* __restrict__ Al0m,
              const __half* __restrict__ Whm, const __half* __restrict__ Wlm,
              float* __restrict__ outm, int Mm, int nblk_g)
{
    extern __shared__ char smem[];
    constexpr int NCH = K / BK;
    const uint32_t sb = smem_u32(smem);

    const int tid  = threadIdx.x;
    const int wid  = tid >> 5;
    const int lane = tid & 31;

    const __half* Ah0 = pAh0;
    const __half* Al0 = pAl0;
    const __half* Wh  = pWh;
    const __half* Wl  = pWl;
    float* out = pout;
    int M = pM;
    int bx = blockIdx.x;
    if (MODE == 0 && bx >= nblk_g) {
        Ah0 = Ah0m; Al0 = Al0m; Wh = Whm; Wl = Wlm; out = outm; M = Mm;
        bx -= nblk_g;
    }
    const int m0 = bx * 128;
    const int n0 = blockIdx.y * 128;

    // stagger co-resident CTAs (bid vs bid+148 differ in bit 2)
    const int start = ((blockIdx.x >> 2) & 1) * (NCH / 2);

    float* s_bias = (float*)(smem);
    float* s_cvec = (float*)(smem + 1024);
    if (MODE != 0) s_bias[tid] = bias[tid];
    if (MODE == 2) s_cvec[tid] = g_cvec[tid & 255];
    __syncthreads();

    auto load_chunk = [&](int buf, int kt) {
        const uint32_t ab = sb + TILES + (uint32_t)buf * BUFB;
        #pragma unroll
        for (int it = 0; it < 2; ++it) {
            int e = it * 256 + tid;
            uint32_t row = (uint32_t)e >> 2;
            uint32_t cq = (uint32_t)e & 3;
            int rr = m0 + (int)row; if (rr >= M) rr = M - 1;
            const __half *ph, *pl;
            int kk;
            if (MODE == 2) {
                size_t r = (size_t)rr * DH;
                if (kt < DH) { ph = Ah0 + r; pl = Al0 + r; kk = kt; }
                else         { ph = Ah1 + r; pl = Al1 + r; kk = kt - DH; }
            } else {
                size_t r = (size_t)rr * DH;
                ph = Ah0 + r; pl = Al0 + r; kk = kt;
            }
            uint32_t off = swz(row, cq);
            CP16(ab + off,        ph + kk + cq * 8);
            CP16(ab + MATB + off, pl + kk + cq * 8);
        }
        #pragma unroll
        for (int it = 0; it < 2; ++it) {
            int e = it * 256 + tid;
            uint32_t row = (uint32_t)e >> 2;
            uint32_t cq = (uint32_t)e & 3;
            size_t g = (size_t)(n0 + (int)row) * ldw + kt + cq * 8;
            uint32_t off = swz(row, cq);
            CP16(ab + 2 * MATB + off, Wh + g);
            CP16(ab + 3 * MATB + off, Wl + g);
        }
        CP_COMMIT();
    };

    const int wm = wid & 3;
    const int wn = wid >> 2;

    const uint32_t rowA = (uint32_t)(wm * 32 + (lane & 15));
    const uint32_t aoff = swz(rowA, (uint32_t)(lane >> 4));
    const uint32_t rowB = (uint32_t)(wn * 64 + ((lane >> 4) & 1) * 8 + (lane & 7));
    const uint32_t boff = swz(rowB, (uint32_t)((lane >> 3) & 1));

    float acc[2][8][4];
    #pragma unroll
    for (int i = 0; i < 2; ++i)
        #pragma unroll
        for (int j = 0; j < 8; ++j)
            #pragma unroll
            for (int q = 0; q < 4; ++q)
                acc[i][j][q] = 0.f;

    load_chunk(0, ((0 + start) & (NCH - 1)) * BK);
    if (NCH > 1) load_chunk(1, ((1 + start) & (NCH - 1)) * BK);

    for (int c = 0; c < NCH; ++c) {
        int buf = c % NSTAGE;
        if (c + 1 < NCH) CP_WAIT1(); else CP_WAIT0();
        __syncthreads();
        if (c + 2 < NCH) load_chunk((c + 2) % NSTAGE, ((c + 2 + start) & (NCH - 1)) * BK);

        const uint32_t tb = sb + TILES + (uint32_t)buf * BUFB;
        #pragma unroll
        for (int s = 0; s < 2; ++s) {
            const uint32_t sx = (uint32_t)s << 5;
            uint32_t ah[2][4], al[2][4];
            LDSM_X4(ah[0], tb + (aoff ^ sx));
            LDSM_X4(ah[1], tb + ((aoff + 1024u) ^ sx));
            LDSM_X4(al[0], tb + MATB + (aoff ^ sx));
            LDSM_X4(al[1], tb + MATB + ((aoff + 1024u) ^ sx));
            #pragma unroll
            for (int p = 0; p < 4; ++p) {
                uint32_t bh[4], bl[4];
                LDSM_X4(bh, tb + 2 * MATB + ((boff + (uint32_t)p * 1024u) ^ sx));
                LDSM_X4(bl, tb + 3 * MATB + ((boff + (uint32_t)p * 1024u) ^ sx));
                MMA16816(acc[0][2*p],   ah[0], bh[0], bh[1]);
                MMA16816(acc[1][2*p],   ah[1], bh[0], bh[1]);
                MMA16816(acc[0][2*p+1], ah[0], bh[2], bh[3]);
                MMA16816(acc[1][2*p+1], ah[1], bh[2], bh[3]);
                MMA16816(acc[0][2*p],   al[0], bh[0], bh[1]);
                MMA16816(acc[1][2*p],   al[1], bh[0], bh[1]);
                MMA16816(acc[0][2*p+1], al[0], bh[2], bh[3]);
                MMA16816(acc[1][2*p+1], al[1], bh[2], bh[3]);
                MMA16816(acc[0][2*p],   ah[0], bl[0], bl[1]);
                MMA16816(acc[1][2*p],   ah[1], bl[0], bl[1]);
                MMA16816(acc[0][2*p+1], ah[0], bl[2], bl[3]);
                MMA16816(acc[1][2*p+1], ah[1], bl[2], bl[3]);
            }
        }
    }
    __syncthreads();

    // ---- epilogue ----
    #pragma unroll
    for (int mt = 0; mt < 2; ++mt) {
        int r0 = m0 + wm * 32 + mt * 16 + (lane >> 2);
        int r1 = r0 + 8;
        float d0 = 0.f, d1 = 0.f;
        if (MODE == 2) {
            if (r0 < M) d0 = g_deg[r0];
            if (r1 < M) d1 = g_deg[r1];
        }
        #pragma unroll
        for (int nt = 0; nt < 8; ++nt) {
            int col = n0 + (wn * 64 + (nt >> 1) * 16 + (nt & 1) * 8) + (lane & 3) * 2;
            float b0 = (MODE != 0) ? s_bias[col & 255] : 0.f;
            float b1 = (MODE != 0) ? s_bias[(col + 1) & 255] : 0.f;
            float v00 = acc[mt][nt][0] + b0, v01 = acc[mt][nt][1] + b1;
            float v10 = acc[mt][nt][2] + b0, v11 = acc[mt][nt][3] + b1;
            if (MODE == 0) {
                if (r0 < M) *(float2*)&out[(size_t)r0 * DH + col] = make_float2(v00, v01);
                if (r1 < M) *(float2*)&out[(size_t)r1 * DH + col] = make_float2(v10, v11);
            } else if (MODE == 2) {
                float c0 = s_cvec[col & 255], c1 = s_cvec[(col + 1) & 255];
                if (r0 < M) {
                    float a = fmaxf(v00 + d0 * c0, 0.f), b = fmaxf(v01 + d0 * c1, 0.f);
                    __half2 hh = __floats2half2_rn(a, b);
                    __half2 ll = __floats2half2_rn(a - __low2float(hh), b - __high2float(hh));
                    *(__half2*)&g_H2h[(size_t)r0 * DH + col] = hh;
                    *(__half2*)&g_H2l[(size_t)r0 * DH + col] = ll;
                }
                if (r1 < M) {
                    float a = fmaxf(v10 + d1 * c0, 0.f), b = fmaxf(v11 + d1 * c1, 0.f);
                    __half2 hh = __floats2half2_rn(a, b);
                    __half2 ll = __floats2half2_rn(a - __low2float(hh), b - __high2float(hh));
                    *(__half2*)&g_H2h[(size_t)r1 * DH + col] = hh;
                    *(__half2*)&g_H2l[(size_t)r1 * DH + col] = ll;
                }
            } else {
                if (r0 < M) {
                    float2 rv = *(const float2*)&resid[(size_t)r0 * DH + col];
                    *(float2*)&out[(size_t)r0 * DH + col] = make_float2(v00 + rv.x, v01 + rv.y);
                }
                if (r1 < M) {
                    float2 rv = *(const float2*)&resid[(size_t)r1 * DH + col];
                    *(float2*)&out[(size_t)r1 * DH + col] = make_float2(v10 + rv.x, v11 + rv.y);
                }
            }
        }
    }
}

// ---------------- launch -----------------------------------------------------------
extern "C" void kernel_launch(void* const* d_in, const int* in_sizes, int n_in,
                              void* d_out, int out_size) {
    const float* mesh_x   = (const float*)d_in[0];
    const float* grid_x   = (const float*)d_in[1];
    const int*   edge_src = (const int*)  d_in[2];
    const int*   edge_dst = (const int*)  d_in[3];
    const float* w1_e = (const float*)d_in[4];
    const float* b1_e = (const float*)d_in[5];
    const float* w2_e = (const float*)d_in[6];
    const float* b2_e = (const float*)d_in[7];
    const float* w1_g = (const float*)d_in[8];
    const float* b1_g = (const float*)d_in[9];
    const float* w2_g = (const float*)d_in[10];
    const float* b2_g = (const float*)d_in[11];
    float* out = (float*)d_out;

    __half *wh, *wl, *mxh, *mxl, *gxh, *gxl, *aggh, *aggl, *h2h, *h2l;
    float *aggf, *mproj, *gproj;
    cudaGetSymbolAddress((void**)&wh,    g_Wh);
    cudaGetSymbolAddress((void**)&wl,    g_Wl);
    cudaGetSymbolAddress((void**)&mxh,   g_mxh);
    cudaGetSymbolAddress((void**)&mxl,   g_mxl);
    cudaGetSymbolAddress((void**)&gxh,   g_gxh);
    cudaGetSymbolAddress((void**)&gxl,   g_gxl);
    cudaGetSymbolAddress((void**)&aggh,  g_aggh);
    cudaGetSymbolAddress((void**)&aggl,  g_aggl);
    cudaGetSymbolAddress((void**)&h2h,   g_H2h);
    cudaGetSymbolAddress((void**)&h2l,   g_H2l);
    cudaGetSymbolAddress((void**)&aggf,  g_agg);
    cudaGetSymbolAddress((void**)&mproj, g_mproj);
    cudaGetSymbolAddress((void**)&gproj, g_gproj);

    __half* wh_e1  = wh;                    __half* wl_e1  = wl;
    __half* wh_cat = wh + 256 * 512;        __half* wl_cat = wl + 256 * 512;
    __half* wh_g2  = wh + 2 * 256 * 512;    __half* wl_g2  = wl + 2 * 256 * 512;

    static bool attr_set = false;
    if (!attr_set) {
        cudaFuncSetAttribute(mma_gemm<0,256>, cudaFuncAttributeMaxDynamicSharedMemorySize, SMEM_SZ);
        cudaFuncSetAttribute(mma_gemm<2,512>, cudaFuncAttributeMaxDynamicSharedMemorySize, SMEM_SZ);
        cudaFuncSetAttribute(mma_gemm<3,256>, cudaFuncAttributeMaxDynamicSharedMemorySize, SMEM_SZ);
        attr_set = true;
    }

    const int GM = (N_MESH + 127) / 128;   // 79
    const int GG = (N_GRID + 127) / 128;   // 782

    // harness issues ~2 launches first; ncu capture = our launch #4
    // 1: zero agg + deg
    zero_kernel<<<25000, 256>>>();
    // 2: split grid_x + mesh_x
    split2_kernel<<<((N_GRID + N_MESH) * DH / 4 + 255) / 256, 256>>>(
        (const float4*)grid_x, (const float4*)mesh_x);
    // 3: W1e transpose+split
    prep_w_kernel<<<dim3(8, 16), dim3(32, 8)>>>(w1_e, wh_e1, wl_e1, 512);
    // 4: merged projections: grid_proj (blocks 0..GG-1) + mesh_proj (GG..GG+GM-1)
    mma_gemm<0,256><<<dim3(GG + GM, 2), 256, SMEM_SZ>>>(
        gxh, gxl, nullptr, nullptr,
        wh_e1 + 256, wl_e1 + 256, 512, nullptr, gproj, nullptr, N_GRID,
        mxh, mxl, wh_e1, wl_e1, mproj, N_MESH, GG);
    // 5: combine + scatter H1 into aggH1, count deg
    combine_kernel<<<N_EDGE / 8, 256>>>(edge_src, edge_dst, b1_e);
    // 6: split aggH1
    split_kernel<<<(N_GRID * DH / 4 + 255) / 256, 256>>>(
        (const float4*)aggf, (uint2*)aggh, (uint2*)aggl, N_GRID * DH / 4);
    // 7: W1g_top transposed into Wcat cols 0..255
    prep_w_kernel<<<dim3(8, 8), dim3(32, 8)>>>(w1_g, wh_cat, wl_cat, 512);
    // 8: Wfused into Wcat cols 256..511 + cvec
    fuse_w_kernel<<<257, 256>>>(w2_e, w1_g, b2_e, wh_cat, wl_cat);
    // 9: grid L1 (fused): relu(gx@W1g_top + aggH1@Wfused + deg*cvec + b1g) -> H2
    mma_gemm<2,512><<<dim3(GG, 2), 256, SMEM_SZ>>>(
        gxh, gxl, aggh, aggl,
        wh_cat, wl_cat, 512, b1_g, nullptr, nullptr, N_GRID,
        nullptr, nullptr, nullptr, nullptr, nullptr, 0, 1 << 30);
    // 10: W2g transpose+split
    prep_w_kernel<<<dim3(8, 8), dim3(32, 8)>>>(w2_g, wh_g2, wl_g2, 256);
    // 11: grid L2 + residual
    mma_gemm<3,256><<<dim3(GG, 2), 256, SMEM_SZ>>>(
        h2h, h2l, nullptr, nullptr,
        wh_g2, wl_g2, 256, b2_g, out, grid_x, N_GRID,
        nullptr, nullptr, nullptr, nullptr, nullptr, 0, 1 << 30);
}